// round 7
// baseline (speedup 1.0000x reference)
#include <cuda_runtime.h>
#include <cuda_bf16.h>
#include <math.h>

#define CN 1024
#define HN 512
#define VN 32000
#define BN 16
#define TN 256
#define SPW 8
#define NCHUNK 15
#define CLEN 17   // 15*17 = 255 step matrices

// ------------------------- scratch (static device memory; no allocs) -------
__device__ __nv_bfloat16 g_tmps[CN * HN];      // relu(l1) start chain
__device__ __nv_bfloat16 g_tmpt[CN * HN];      // relu(l1) trans chain
__device__ __nv_bfloat16 g_tmpp[CN * HN];      // relu(l1) term chain
__device__ __nv_bfloat16 g_htb[CN * HN];       // trans residual out (bf16)
__device__ __nv_bfloat16 g_hpb[CN * HN];       // term residual out (bf16)
__device__ float g_sl[CN];                     // start logits (bias + fused head dots)
__device__ float g_slse;                       // lse of start logits
__device__ float g_trans[CN * CN];             // raw trans logits
__device__ float g_rowsum[CN];                 // per-row sum(exp(trans)) (no max; safe)
__device__ float g_pair[VN * SPW];             // term pair logits
__device__ float g_sumb[CN];                   // sum exp(logit) per state
__device__ float g_chunk[BN * NCHUNK * 64];    // chunk products
__device__ float g_ev[BN];
__device__ unsigned g_cnt1;
__device__ unsigned g_cnt2;

// ---------------------------------------------------------------------------
// bf16 tensor-core GEMM core v3: CTA tile 64x64, 128 threads (4 warps 2x2),
// warp tile 32x32, K-step 32, ldmatrix fragment loads.
// Optional fused epilogues: headw (row-dot -> atomicAdd g_sl),
// rowsum (atomicAdd per-row sum of expf(out)).
// ---------------------------------------------------------------------------
__device__ __forceinline__ void mma16816(float* d, const unsigned* a, const unsigned* b) {
    asm volatile(
        "mma.sync.aligned.m16n8k16.row.col.f32.bf16.bf16.f32 "
        "{%0,%1,%2,%3}, {%4,%5,%6,%7}, {%8,%9}, {%0,%1,%2,%3};\n"
        : "+f"(d[0]), "+f"(d[1]), "+f"(d[2]), "+f"(d[3])
        : "r"(a[0]), "r"(a[1]), "r"(a[2]), "r"(a[3]), "r"(b[0]), "r"(b[1]));
}

__device__ __forceinline__ void ldsm4(unsigned& r0, unsigned& r1, unsigned& r2,
                                      unsigned& r3, unsigned addr) {
    asm volatile(
        "ldmatrix.sync.aligned.m8n8.x4.shared.b16 {%0,%1,%2,%3}, [%4];"
        : "=r"(r0), "=r"(r1), "=r"(r2), "=r"(r3) : "r"(addr));
}

#define SSTRIDE 40  // bf16 elems per smem row (80B): conflict-free ldmatrix

template <bool ABF>
__device__ __forceinline__ void gemm_core(
    const float* __restrict__ Af, const __nv_bfloat16* __restrict__ Ab,
    const float* __restrict__ W, const float* __restrict__ bias,
    const float* __restrict__ res, float* __restrict__ outF,
    __nv_bfloat16* __restrict__ outB, const float* __restrict__ headw,
    float* __restrict__ rowsum, int N, int K, int relu)
{
    __shared__ __nv_bfloat16 sA[64 * SSTRIDE];
    __shared__ __nv_bfloat16 sB[64 * SSTRIDE];

    const int t = threadIdx.x;                // 0..127
    const int lane = t & 31, warp = t >> 5;
    const int wm = warp >> 1, wn = warp & 1;  // 2x2 warp grid
    const int row0 = blockIdx.y * 64, col0 = blockIdx.x * 64;
    const int lr = lane >> 2, lc = lane & 3;

    // ldmatrix lane addresses (bytes, shared space)
    const unsigned sAu = (unsigned)__cvta_generic_to_shared(sA);
    const unsigned sBu = (unsigned)__cvta_generic_to_shared(sB);
    const int arow = lane & 15, ahalf = (lane >> 4) << 3;
    const unsigned aAddr0 = sAu + (((wm * 32 + arow) * SSTRIDE + ahalf) << 1);
    const unsigned aAddr1 = sAu + (((wm * 32 + 16 + arow) * SSTRIDE + ahalf) << 1);
    const int brow = (lane & 7) + ((lane >> 4) << 3);
    const int bhalf = ((lane >> 3) & 1) << 3;
    const unsigned bAddr0 = sBu + (((wn * 32 + brow) * SSTRIDE + bhalf) << 1);
    const unsigned bAddr1 = sBu + (((wn * 32 + 16 + brow) * SSTRIDE + bhalf) << 1);

    float acc[2][4][4];
#pragma unroll
    for (int mt = 0; mt < 2; mt++)
#pragma unroll
        for (int nt = 0; nt < 4; nt++)
#pragma unroll
            for (int q = 0; q < 4; q++) acc[mt][nt][q] = 0.f;

    float4 pa[4];
    uint2 pab[4];
    float4 pw[4];

#pragma unroll
    for (int i = 0; i < 4; i++) {
        int id = i * 128 + t, r = id >> 3, c4 = id & 7;
        if (ABF)
            pab[i] = *(const uint2*)(Ab + (size_t)(row0 + r) * K + c4 * 4);
        else
            pa[i] = *(const float4*)(Af + (size_t)(row0 + r) * K + c4 * 4);
        pw[i] = *(const float4*)(W + (size_t)(col0 + r) * K + c4 * 4);
    }

    const int NT = K / 32;
    for (int kt = 0; kt < NT; kt++) {
#pragma unroll
        for (int i = 0; i < 4; i++) {
            int id = i * 128 + t, r = id >> 3, c4 = id & 7;
            __nv_bfloat16* da = &sA[r * SSTRIDE + c4 * 4];
            if (ABF) {
                *(unsigned*)da = pab[i].x;
                *(unsigned*)(da + 2) = pab[i].y;
            } else {
                *(__nv_bfloat162*)da = __float22bfloat162_rn(make_float2(pa[i].x, pa[i].y));
                *(__nv_bfloat162*)(da + 2) = __float22bfloat162_rn(make_float2(pa[i].z, pa[i].w));
            }
            __nv_bfloat16* dw = &sB[r * SSTRIDE + c4 * 4];
            *(__nv_bfloat162*)dw = __float22bfloat162_rn(make_float2(pw[i].x, pw[i].y));
            *(__nv_bfloat162*)(dw + 2) = __float22bfloat162_rn(make_float2(pw[i].z, pw[i].w));
        }
        __syncthreads();

        int kn = (kt + 1) * 32;
        if (kn < K) {
#pragma unroll
            for (int i = 0; i < 4; i++) {
                int id = i * 128 + t, r = id >> 3, c4 = id & 7;
                if (ABF)
                    pab[i] = *(const uint2*)(Ab + (size_t)(row0 + r) * K + kn + c4 * 4);
                else
                    pa[i] = *(const float4*)(Af + (size_t)(row0 + r) * K + kn + c4 * 4);
                pw[i] = *(const float4*)(W + (size_t)(col0 + r) * K + kn + c4 * 4);
            }
        }

#pragma unroll
        for (int kk = 0; kk < 2; kk++) {
            const unsigned off = kk * 32;  // 16 bf16 = 32 bytes along k
            unsigned af[2][4], bfr[4][2];
            ldsm4(af[0][0], af[0][1], af[0][2], af[0][3], aAddr0 + off);
            ldsm4(af[1][0], af[1][1], af[1][2], af[1][3], aAddr1 + off);
            ldsm4(bfr[0][0], bfr[0][1], bfr[1][0], bfr[1][1], bAddr0 + off);
            ldsm4(bfr[2][0], bfr[2][1], bfr[3][0], bfr[3][1], bAddr1 + off);
#pragma unroll
            for (int mt = 0; mt < 2; mt++)
#pragma unroll
                for (int nt = 0; nt < 4; nt++) mma16816(acc[mt][nt], af[mt], bfr[nt]);
        }
        __syncthreads();
    }

    float part[2][2] = {{0.f, 0.f}, {0.f, 0.f}};
    float rs[2][2] = {{0.f, 0.f}, {0.f, 0.f}};
#pragma unroll
    for (int mt = 0; mt < 2; mt++)
#pragma unroll
        for (int nt = 0; nt < 4; nt++) {
            int gr = row0 + wm * 32 + mt * 16 + lr;
            int gc = col0 + wn * 32 + nt * 8 + lc * 2;
            float2 b2 = make_float2(0.f, 0.f);
            if (bias) b2 = *(const float2*)(bias + gc);
#pragma unroll
            for (int h = 0; h < 2; h++) {
                int r_ = gr + h * 8;
                float v0 = acc[mt][nt][h * 2 + 0] + b2.x;
                float v1 = acc[mt][nt][h * 2 + 1] + b2.y;
                if (relu) { v0 = fmaxf(v0, 0.f); v1 = fmaxf(v1, 0.f); }
                if (res) {
                    float2 r2 = *(const float2*)(res + (size_t)r_ * N + gc);
                    v0 += r2.x; v1 += r2.y;
                }
                if (headw) {
                    float2 wv = *(const float2*)(headw + gc);
                    part[mt][h] = fmaf(v0, wv.x, fmaf(v1, wv.y, part[mt][h]));
                }
                if (rowsum) rs[mt][h] += __expf(v0) + __expf(v1);
                if (outF) *(float2*)(outF + (size_t)r_ * N + gc) = make_float2(v0, v1);
                if (outB)
                    *(__nv_bfloat162*)(outB + (size_t)r_ * N + gc) =
                        __float22bfloat162_rn(make_float2(v0, v1));
            }
        }
    if (headw || rowsum) {
#pragma unroll
        for (int mt = 0; mt < 2; mt++)
#pragma unroll
            for (int h = 0; h < 2; h++) {
                float p = headw ? part[mt][h] : rs[mt][h];
                p += __shfl_xor_sync(0xffffffffu, p, 1);
                p += __shfl_xor_sync(0xffffffffu, p, 2);
                if (lc == 0) {
                    int r_ = row0 + wm * 32 + mt * 16 + lr + h * 8;
                    atomicAdd(headw ? &g_sl[r_] : &rowsum[r_], p);
                }
            }
    }
}

// ---------------- per-chain GEMM kernels (3 streams) -----------------------
// layer 1: out = relu(A @ W^T + b), bf16. init: 1=trans scratch, 2=term, 3=start.
__global__ __launch_bounds__(128) void k_l1(
    const float* __restrict__ A, const float* __restrict__ W,
    const float* __restrict__ B, __nv_bfloat16* __restrict__ out,
    int init, const float* __restrict__ ob)
{
    if (blockIdx.x == 0 && blockIdx.y == 0) {
        if (init == 1) {
            for (int i = threadIdx.x; i < CN; i += 128) g_rowsum[i] = 0.f;
            if (threadIdx.x == 0) { g_cnt1 = 0u; g_cnt2 = 0u; }
        } else if (init == 2) {
            for (int i = threadIdx.x; i < CN; i += 128) g_sumb[i] = 0.f;
        } else if (init == 3) {
            float ob0 = ob[0];
            for (int i = threadIdx.x; i < CN; i += 128) g_sl[i] = ob0;
        }
    }
    gemm_core<false>(A, nullptr, W, B, nullptr, nullptr, out, nullptr, nullptr,
                     HN, HN, 1);
}

// layer 2: out = res + relu(tmp @ W^T + b); headw fuses the start head.
__global__ __launch_bounds__(128) void k_l2(
    const __nv_bfloat16* __restrict__ tmp, const float* __restrict__ W,
    const float* __restrict__ B, const float* __restrict__ res,
    __nv_bfloat16* __restrict__ out, const float* __restrict__ headw)
{
    gemm_core<true>(nullptr, tmp, W, B, res, nullptr, out, headw, nullptr,
                    HN, HN, 1);
}

// trans projection: g_trans = g_htb @ proj_w^T, fused row exp-sums.
__global__ __launch_bounds__(128) void k_proj(const float* __restrict__ W)
{
    gemm_core<true>(nullptr, g_htb, W, nullptr, nullptr, g_trans, nullptr, nullptr,
                    g_rowsum, CN, HN, 0);
}

// ---------------------------------------------------------------------------
// term sparse stage: one block per word; 8 pair logits + dedup'd exp-sums.
// ---------------------------------------------------------------------------
__global__ __launch_bounds__(256) void term_pair_k(
    const float* __restrict__ tow, const float* __restrict__ tob,
    const int* __restrict__ w2s)
{
    __shared__ float ws[HN];
    __shared__ int cs[SPW];
    int v = blockIdx.x, tid = threadIdx.x;
    for (int i = tid; i < HN / 4; i += 256)
        ((float4*)ws)[i] = ((const float4*)(tow + (size_t)v * HN))[i];
    if (tid < SPW) cs[tid] = w2s[v * SPW + tid];
    __syncthreads();
    int warp = tid >> 5, lane = tid & 31;
    int c = cs[warp];
    const uint4* h4 = (const uint4*)(g_hpb + (size_t)c * HN);
    const float4* wsv = (const float4*)ws;
    float s = 0.f;
#pragma unroll
    for (int it = 0; it < 2; it++) {
        int idx = it * 32 + lane;
        uint4 q = h4[idx];
        float4 w0 = wsv[idx * 2], w1 = wsv[idx * 2 + 1];
        __nv_bfloat162 p0 = *(__nv_bfloat162*)&q.x;
        __nv_bfloat162 p1 = *(__nv_bfloat162*)&q.y;
        __nv_bfloat162 p2 = *(__nv_bfloat162*)&q.z;
        __nv_bfloat162 p3 = *(__nv_bfloat162*)&q.w;
        s = fmaf(__low2float(p0), w0.x, s);
        s = fmaf(__high2float(p0), w0.y, s);
        s = fmaf(__low2float(p1), w0.z, s);
        s = fmaf(__high2float(p1), w0.w, s);
        s = fmaf(__low2float(p2), w1.x, s);
        s = fmaf(__high2float(p2), w1.y, s);
        s = fmaf(__low2float(p3), w1.z, s);
        s = fmaf(__high2float(p3), w1.w, s);
    }
#pragma unroll
    for (int o = 16; o; o >>= 1) s += __shfl_xor_sync(0xffffffffu, s, o);
    if (lane == 0) {
        float logit = s + tob[v];
        g_pair[v * SPW + warp] = logit;
        bool dup = false;
        for (int k2 = 0; k2 < warp; k2++) if (cs[k2] == c) dup = true;
        if (!dup) atomicAdd(&g_sumb[c], __expf(logit));
    }
}

// ---------------------------------------------------------------------------
// fused parallel scan (unchanged from R5)
// ---------------------------------------------------------------------------
__global__ __launch_bounds__(64) void scan_all_k(
    const int* __restrict__ text, const int* __restrict__ w2s,
    float* __restrict__ out)
{
    __shared__ int sw[CLEN + 1];
    __shared__ int sws[CLEN + 1][8];
    __shared__ float emi[CLEN + 1][8];
    __shared__ float rlz[CLEN + 1][8];
    __shared__ float bufA[64], bufB[64], sM[64];
    __shared__ float red2[2];

    int c = blockIdx.x, b = blockIdx.y, tid = threadIdx.x;
    int base = b * TN + c * CLEN;

    if (tid < CLEN + 1) sw[tid] = text[base + tid];
    __syncthreads();
    for (int idx = tid; idx < (CLEN + 1) * 8; idx += 64) {
        int s = idx >> 3, j = idx & 7;
        int st = w2s[sw[s] * 8 + j];
        sws[s][j] = st;
        rlz[s][j] = __logf(g_rowsum[st]);
        if (s >= 1) emi[s][j] = g_pair[sw[s] * 8 + j] - __logf(g_sumb[st]);
    }
    __syncthreads();

    int j = tid >> 3, i = tid & 7;
    float* cur = bufA;
    float* nxt = bufB;
    cur[tid] = g_trans[(size_t)sws[0][i] * CN + sws[1][j]] - rlz[0][i] + emi[1][j];
    float pend = g_trans[(size_t)sws[1][i] * CN + sws[2][j]] - rlz[1][i] + emi[2][j];
    __syncthreads();

    for (int s = 1; s < CLEN; s++) {
        sM[tid] = pend;
        if (s + 1 < CLEN)
            pend = g_trans[(size_t)sws[s + 1][i] * CN + sws[s + 2][j]]
                   - rlz[s + 1][i] + emi[s + 2][j];
        __syncthreads();
        const float* Mr = &sM[j << 3];
        float v0 = Mr[0] + cur[0 * 8 + i];
        float v1 = Mr[1] + cur[1 * 8 + i];
        float v2 = Mr[2] + cur[2 * 8 + i];
        float v3 = Mr[3] + cur[3 * 8 + i];
        float v4 = Mr[4] + cur[4 * 8 + i];
        float v5 = Mr[5] + cur[5 * 8 + i];
        float v6 = Mr[6] + cur[6 * 8 + i];
        float v7 = Mr[7] + cur[7 * 8 + i];
        float m = fmaxf(fmaxf(fmaxf(v0, v1), fmaxf(v2, v3)),
                        fmaxf(fmaxf(v4, v5), fmaxf(v6, v7)));
        float sum = ((__expf(v0 - m) + __expf(v1 - m)) + (__expf(v2 - m) + __expf(v3 - m))) +
                    ((__expf(v4 - m) + __expf(v5 - m)) + (__expf(v6 - m) + __expf(v7 - m)));
        nxt[tid] = m + __logf(sum);
        __syncthreads();
        float* tp = cur; cur = nxt; nxt = tp;
    }
    g_chunk[((size_t)b * NCHUNK + c) * 64 + tid] = cur[tid];
    __threadfence();
    __syncthreads();

    if (c == 1 && b == 0) {
        const float4* sl4 = (const float4*)g_sl;
        float es = 0.f;
#pragma unroll
        for (int q = 0; q < 4; q++) {
            float4 v = sl4[tid * 4 + q];
            es += __expf(v.x) + __expf(v.y) + __expf(v.z) + __expf(v.w);
        }
#pragma unroll
        for (int o = 16; o; o >>= 1) es += __shfl_xor_sync(0xffffffffu, es, o);
        if ((tid & 31) == 0) red2[tid >> 5] = es;
        __syncthreads();
        if (tid == 0) {
            g_slse = __logf(red2[0] + red2[1]);
            __threadfence();
        }
        __syncthreads();
    }
    if (tid == 0) atomicAdd(&g_cnt1, 1u);
    if (c != 0) return;

    if (tid == 0) {
        while (atomicAdd(&g_cnt1, 0u) < (unsigned)(NCHUNK * BN)) __nanosleep(64);
    }
    __syncthreads();
    __threadfence();

    if (tid < 8) {
        int c0 = sws[0][tid];
        float an = g_sl[c0] - g_slse + g_pair[sw[0] * 8 + tid] - __logf(g_sumb[c0]);
        float a[8];
#pragma unroll
        for (int q = 0; q < 8; q++) a[q] = __shfl_sync(0xFFu, an, q);
        for (int cc = 0; cc < NCHUNK; cc++) {
            const float4* p4 =
                (const float4*)(g_chunk + ((size_t)b * NCHUNK + cc) * 64 + (tid << 3));
            float4 pA = p4[0], pB = p4[1];
            float v0 = pA.x + a[0], v1 = pA.y + a[1], v2 = pA.z + a[2], v3 = pA.w + a[3];
            float v4 = pB.x + a[4], v5 = pB.y + a[5], v6 = pB.z + a[6], v7 = pB.w + a[7];
            float m = fmaxf(fmaxf(fmaxf(v0, v1), fmaxf(v2, v3)),
                            fmaxf(fmaxf(v4, v5), fmaxf(v6, v7)));
            float s = ((__expf(v0 - m) + __expf(v1 - m)) + (__expf(v2 - m) + __expf(v3 - m))) +
                      ((__expf(v4 - m) + __expf(v5 - m)) + (__expf(v6 - m) + __expf(v7 - m)));
            an = m + __logf(s);
#pragma unroll
            for (int q = 0; q < 8; q++) a[q] = __shfl_sync(0xFFu, an, q);
        }
        if (tid == 0) {
            float m = a[0];
#pragma unroll
            for (int q = 1; q < 8; q++) m = fmaxf(m, a[q]);
            float s = 0.f;
#pragma unroll
            for (int q = 0; q < 8; q++) s += __expf(a[q] - m);
            g_ev[b] = m + __logf(s);
            __threadfence();
            atomicAdd(&g_cnt2, 1u);
        }
    }
    if (b != 0) return;

    if (tid == 0) {
        while (atomicAdd(&g_cnt2, 0u) < (unsigned)BN) __nanosleep(64);
        __threadfence();
        float s = 0.f;
#pragma unroll
        for (int q = 0; q < BN; q++) s += g_ev[q];
        out[0] = s;
    }
}

// ---------------------------------------------------------------------------
extern "C" void kernel_launch(void* const* d_in, const int* in_sizes, int n_in,
                              void* d_out, int out_size)
{
    const float* start_emb = (const float*)d_in[0];
    const float* start_l1w = (const float*)d_in[1];
    const float* start_l1b = (const float*)d_in[2];
    const float* start_l2w = (const float*)d_in[3];
    const float* start_l2b = (const float*)d_in[4];
    const float* start_ow  = (const float*)d_in[5];
    const float* start_ob  = (const float*)d_in[6];
    const float* state_emb = (const float*)d_in[7];
    const float* trans_l1w = (const float*)d_in[8];
    const float* trans_l1b = (const float*)d_in[9];
    const float* trans_l2w = (const float*)d_in[10];
    const float* trans_l2b = (const float*)d_in[11];
    const float* proj_w    = (const float*)d_in[12];
    const float* pret_emb  = (const float*)d_in[13];
    const float* term_l1w  = (const float*)d_in[14];
    const float* term_l1b  = (const float*)d_in[15];
    const float* term_l2w  = (const float*)d_in[16];
    const float* term_l2b  = (const float*)d_in[17];
    const float* term_ow   = (const float*)d_in[18];
    const float* term_ob   = (const float*)d_in[19];
    const int*   text      = (const int*)d_in[20];
    const int*   w2s       = (const int*)d_in[21];
    float* out = (float*)d_out;

    // one-time infra (no device memory): side streams + fork/join events
    static cudaStream_t s1 = nullptr, s2 = nullptr;
    static cudaEvent_t ev0 = nullptr, evB = nullptr, evC = nullptr;
    if (s1 == nullptr) {
        cudaStreamCreateWithFlags(&s1, cudaStreamNonBlocking);
        cudaStreamCreateWithFlags(&s2, cudaStreamNonBlocking);
        cudaEventCreateWithFlags(&ev0, cudaEventDisableTiming);
        cudaEventCreateWithFlags(&evB, cudaEventDisableTiming);
        cudaEventCreateWithFlags(&evC, cudaEventDisableTiming);
    }
    cudaStream_t s0 = (cudaStream_t)0;  // legacy stream (what the harness captures)

    dim3 gH(HN / 64, CN / 64);   // 8 x 16
    dim3 gC(CN / 64, CN / 64);   // 16 x 16

    // fork
    cudaEventRecord(ev0, s0);
    cudaStreamWaitEvent(s1, ev0, 0);
    cudaStreamWaitEvent(s2, ev0, 0);

    // s0: trans chain (+ counters/rowsum init)
    k_l1<<<gH, 128, 0, s0>>>(state_emb, trans_l1w, trans_l1b, g_tmpt, 1, nullptr);
    k_l2<<<gH, 128, 0, s0>>>(g_tmpt, trans_l2w, trans_l2b, state_emb, g_htb, nullptr);
    k_proj<<<gC, 128, 0, s0>>>(proj_w);

    // s1: term chain (+ sumb init)
    k_l1<<<gH, 128, 0, s1>>>(pret_emb, term_l1w, term_l1b, g_tmpp, 2, nullptr);
    k_l2<<<gH, 128, 0, s1>>>(g_tmpp, term_l2w, term_l2b, pret_emb, g_hpb, nullptr);
    term_pair_k<<<VN, 256, 0, s1>>>(term_ow, term_ob, w2s);
    cudaEventRecord(evB, s1);

    // s2: start chain (+ g_sl init), head fused into l2 epilogue
    k_l1<<<gH, 128, 0, s2>>>(start_emb, start_l1w, start_l1b, g_tmps, 3, start_ob);
    k_l2<<<gH, 128, 0, s2>>>(g_tmps, start_l2w, start_l2b, start_emb, nullptr, start_ow);
    cudaEventRecord(evC, s2);

    // join, then fused parallel scan + final evidence
    cudaStreamWaitEvent(s0, evB, 0);
    cudaStreamWaitEvent(s0, evC, 0);
    scan_all_k<<<dim3(NCHUNK, BN), 64, 0, s0>>>(text, w2s, out);
}

// round 8
// speedup vs baseline: 2.7300x; 2.7300x over previous
#include <cuda_runtime.h>
#include <cuda_bf16.h>
#include <math.h>

#define CN 1024
#define HN 512
#define VN 32000
#define BN 16
#define TN 256
#define SPW 8
#define NCHUNK 15
#define CLEN 17   // 15*17 = 255 step matrices

// ------------------------- scratch (static device memory; no allocs) -------
__device__ __nv_bfloat16 g_tmpb[3 * CN * HN];  // relu(layer1) per chain, bf16
__device__ __nv_bfloat16 g_htb[CN * HN];       // trans residual out (bf16)
__device__ __nv_bfloat16 g_hpb[CN * HN];       // term residual out (bf16)
__device__ float g_sl[CN];                     // start logits (bias + fused head dots)
__device__ float g_startlp[CN];                // start log-probs
__device__ float g_trans[CN * CN];             // raw trans logits
__device__ float g_rowlz[CN];                  // per-row logZ of g_trans
__device__ float g_pair[VN * SPW];             // term pair logits
__device__ float g_sumb[CN];                   // sum exp(logit) per state
__device__ float g_chunk[BN * NCHUNK * 64];    // chunk products
__device__ float g_ev[BN];
__device__ unsigned g_cnt1;
__device__ unsigned g_cnt2;

// ---------------------------------------------------------------------------
// bf16 tensor-core GEMM core (R4-proven): CTA 64x64, 128 threads, 2x2 warps,
// warp tile 32x32, K-step 32, register-prefetch, manual LDS fragment loads.
// Optional fused "head" epilogue: row-dot with headw -> atomicAdd g_sl[row].
// ---------------------------------------------------------------------------
__device__ __forceinline__ void mma16816(float* d, const unsigned* a, const unsigned* b) {
    asm volatile(
        "mma.sync.aligned.m16n8k16.row.col.f32.bf16.bf16.f32 "
        "{%0,%1,%2,%3}, {%4,%5,%6,%7}, {%8,%9}, {%0,%1,%2,%3};\n"
        : "+f"(d[0]), "+f"(d[1]), "+f"(d[2]), "+f"(d[3])
        : "r"(a[0]), "r"(a[1]), "r"(a[2]), "r"(a[3]), "r"(b[0]), "r"(b[1]));
}

#define SSTRIDE 40  // bf16 elems per smem row (80B) -> conflict-free frag loads

template <bool ABF>
__device__ __forceinline__ void gemm_core(
    const float* __restrict__ Af, const __nv_bfloat16* __restrict__ Ab,
    const float* __restrict__ W, const float* __restrict__ bias,
    const float* __restrict__ res, float* __restrict__ outF,
    __nv_bfloat16* __restrict__ outB, const float* __restrict__ headw,
    int N, int K, int relu)
{
    __shared__ __nv_bfloat16 sA[64 * SSTRIDE];
    __shared__ __nv_bfloat16 sB[64 * SSTRIDE];

    const int t = threadIdx.x;
    const int lane = t & 31, warp = t >> 5;
    const int wm = warp >> 1, wn = warp & 1;
    const int row0 = blockIdx.y * 64, col0 = blockIdx.x * 64;
    const int lr = lane >> 2, lc = lane & 3;

    float acc[2][4][4];
#pragma unroll
    for (int mt = 0; mt < 2; mt++)
#pragma unroll
        for (int nt = 0; nt < 4; nt++)
#pragma unroll
            for (int q = 0; q < 4; q++) acc[mt][nt][q] = 0.f;

    float4 pa[4];
    uint2 pab[4];
    float4 pw[4];

#pragma unroll
    for (int i = 0; i < 4; i++) {
        int id = i * 128 + t, r = id >> 3, c4 = id & 7;
        if (ABF)
            pab[i] = *(const uint2*)(Ab + (size_t)(row0 + r) * K + c4 * 4);
        else
            pa[i] = *(const float4*)(Af + (size_t)(row0 + r) * K + c4 * 4);
        pw[i] = *(const float4*)(W + (size_t)(col0 + r) * K + c4 * 4);
    }

    const int NT = K / 32;
    for (int kt = 0; kt < NT; kt++) {
#pragma unroll
        for (int i = 0; i < 4; i++) {
            int id = i * 128 + t, r = id >> 3, c4 = id & 7;
            __nv_bfloat16* da = &sA[r * SSTRIDE + c4 * 4];
            if (ABF) {
                *(unsigned*)da = pab[i].x;
                *(unsigned*)(da + 2) = pab[i].y;
            } else {
                *(__nv_bfloat162*)da = __float22bfloat162_rn(make_float2(pa[i].x, pa[i].y));
                *(__nv_bfloat162*)(da + 2) = __float22bfloat162_rn(make_float2(pa[i].z, pa[i].w));
            }
            __nv_bfloat16* dw = &sB[r * SSTRIDE + c4 * 4];
            *(__nv_bfloat162*)dw = __float22bfloat162_rn(make_float2(pw[i].x, pw[i].y));
            *(__nv_bfloat162*)(dw + 2) = __float22bfloat162_rn(make_float2(pw[i].z, pw[i].w));
        }
        __syncthreads();

        int kn = (kt + 1) * 32;
        if (kn < K) {
#pragma unroll
            for (int i = 0; i < 4; i++) {
                int id = i * 128 + t, r = id >> 3, c4 = id & 7;
                if (ABF)
                    pab[i] = *(const uint2*)(Ab + (size_t)(row0 + r) * K + kn + c4 * 4);
                else
                    pa[i] = *(const float4*)(Af + (size_t)(row0 + r) * K + kn + c4 * 4);
                pw[i] = *(const float4*)(W + (size_t)(col0 + r) * K + kn + c4 * 4);
            }
        }

#pragma unroll
        for (int kk = 0; kk < 2; kk++) {
            unsigned af[2][4], bfr[4][2];
            int kb = kk * 16 + lc * 2;
#pragma unroll
            for (int mt = 0; mt < 2; mt++) {
                const __nv_bfloat16* p = &sA[(wm * 32 + mt * 16 + lr) * SSTRIDE + kb];
                af[mt][0] = *(const unsigned*)p;
                af[mt][1] = *(const unsigned*)(p + 8 * SSTRIDE);
                af[mt][2] = *(const unsigned*)(p + 8);
                af[mt][3] = *(const unsigned*)(p + 8 * SSTRIDE + 8);
            }
#pragma unroll
            for (int nt = 0; nt < 4; nt++) {
                const __nv_bfloat16* p = &sB[(wn * 32 + nt * 8 + lr) * SSTRIDE + kb];
                bfr[nt][0] = *(const unsigned*)p;
                bfr[nt][1] = *(const unsigned*)(p + 8);
            }
#pragma unroll
            for (int mt = 0; mt < 2; mt++)
#pragma unroll
                for (int nt = 0; nt < 4; nt++) mma16816(acc[mt][nt], af[mt], bfr[nt]);
        }
        __syncthreads();
    }

    float part[2][2] = {{0.f, 0.f}, {0.f, 0.f}};
#pragma unroll
    for (int mt = 0; mt < 2; mt++)
#pragma unroll
        for (int nt = 0; nt < 4; nt++) {
            int gr = row0 + wm * 32 + mt * 16 + lr;
            int gc = col0 + wn * 32 + nt * 8 + lc * 2;
            float2 b2 = make_float2(0.f, 0.f);
            if (bias) b2 = *(const float2*)(bias + gc);
#pragma unroll
            for (int h = 0; h < 2; h++) {
                int r_ = gr + h * 8;
                float v0 = acc[mt][nt][h * 2 + 0] + b2.x;
                float v1 = acc[mt][nt][h * 2 + 1] + b2.y;
                if (relu) { v0 = fmaxf(v0, 0.f); v1 = fmaxf(v1, 0.f); }
                if (res) {
                    float2 r2 = *(const float2*)(res + (size_t)r_ * N + gc);
                    v0 += r2.x; v1 += r2.y;
                }
                if (headw) {
                    float2 wv = *(const float2*)(headw + gc);
                    part[mt][h] = fmaf(v0, wv.x, fmaf(v1, wv.y, part[mt][h]));
                }
                if (outF) *(float2*)(outF + (size_t)r_ * N + gc) = make_float2(v0, v1);
                if (outB)
                    *(__nv_bfloat162*)(outB + (size_t)r_ * N + gc) =
                        __float22bfloat162_rn(make_float2(v0, v1));
            }
        }
    if (headw) {
#pragma unroll
        for (int mt = 0; mt < 2; mt++)
#pragma unroll
            for (int h = 0; h < 2; h++) {
                float p = part[mt][h];
                p += __shfl_xor_sync(0xffffffffu, p, 1);
                p += __shfl_xor_sync(0xffffffffu, p, 2);
                if (lc == 0) {
                    int r_ = row0 + wm * 32 + mt * 16 + lr + h * 8;
                    atomicAdd(&g_sl[r_], p);
                }
            }
    }
}

// layer 1 (batched over z=3 chains). Block (0,0,0) also initializes scratch.
__global__ __launch_bounds__(128) void gemm_l1_k(
    const float* A0, const float* A1, const float* A2,
    const float* W0, const float* W1, const float* W2,
    const float* B0, const float* B1, const float* B2,
    const float* ob)
{
    int z = blockIdx.z;
    if (z == 0 && blockIdx.x == 0 && blockIdx.y == 0) {
        float ob0 = ob[0];
        for (int i = threadIdx.x; i < CN; i += 128) {
            g_sl[i] = ob0;
            g_sumb[i] = 0.f;
        }
        if (threadIdx.x == 0) { g_cnt1 = 0u; g_cnt2 = 0u; }
    }
    const float* A = z == 0 ? A0 : (z == 1 ? A1 : A2);
    const float* W = z == 0 ? W0 : (z == 1 ? W1 : W2);
    const float* B = z == 0 ? B0 : (z == 1 ? B1 : B2);
    gemm_core<false>(A, nullptr, W, B, nullptr, nullptr,
                     g_tmpb + (size_t)z * CN * HN, nullptr, HN, HN, 1);
}

// layer 2 (batched). z0: head-fused (no store). z1 -> g_htb. z2 -> g_hpb.
__global__ __launch_bounds__(128) void gemm_l2_k(
    const float* W0, const float* W1, const float* W2,
    const float* B0, const float* B1, const float* B2,
    const float* R0, const float* R1, const float* R2,
    const float* ow)
{
    int z = blockIdx.z;
    const float* W = z == 0 ? W0 : (z == 1 ? W1 : W2);
    const float* B = z == 0 ? B0 : (z == 1 ? B1 : B2);
    const float* R = z == 0 ? R0 : (z == 1 ? R1 : R2);
    __nv_bfloat16* oB = z == 0 ? nullptr : (z == 1 ? g_htb : g_hpb);
    const float* hw = z == 0 ? ow : nullptr;
    gemm_core<true>(nullptr, g_tmpb + (size_t)z * CN * HN, W, B, R, nullptr, oB, hw,
                    HN, HN, 1);
}

// trans projection: g_trans = g_htb @ proj_w^T  (1024x1024x512), A in bf16
__global__ __launch_bounds__(128) void gemm_proj_k(const float* W)
{
    gemm_core<true>(nullptr, g_htb, W, nullptr, nullptr, g_trans, nullptr, nullptr,
                    CN, HN, 0);
}

// ---------------------------------------------------------------------------
// row logsumexp of g_trans (blocks 0..CN-1 -> g_rowlz[row]);
// block CN: start log_softmax over g_sl -> g_startlp.
// ---------------------------------------------------------------------------
__global__ __launch_bounds__(256) void rowlse_k()
{
    __shared__ float red[8];
    __shared__ float bc;
    int row = blockIdx.x, t = threadIdx.x;
    const float* src = (row == CN) ? g_sl : (g_trans + (size_t)row * CN);
    float4 v = ((const float4*)src)[t];
    float m = fmaxf(fmaxf(v.x, v.y), fmaxf(v.z, v.w));
#pragma unroll
    for (int o = 16; o; o >>= 1) m = fmaxf(m, __shfl_xor_sync(0xffffffffu, m, o));
    if ((t & 31) == 0) red[t >> 5] = m;
    __syncthreads();
    if (t < 8) {
        float x = red[t];
#pragma unroll
        for (int o = 4; o; o >>= 1) x = fmaxf(x, __shfl_xor_sync(0xffu, x, o));
        if (t == 0) bc = x;
    }
    __syncthreads();
    m = bc;
    float e = __expf(v.x - m) + __expf(v.y - m) + __expf(v.z - m) + __expf(v.w - m);
#pragma unroll
    for (int o = 16; o; o >>= 1) e += __shfl_xor_sync(0xffffffffu, e, o);
    __syncthreads();
    if ((t & 31) == 0) red[t >> 5] = e;
    __syncthreads();
    if (t < 8) {
        float x = red[t];
#pragma unroll
        for (int o = 4; o; o >>= 1) x += __shfl_xor_sync(0xffu, x, o);
        if (t == 0) bc = x;
    }
    __syncthreads();
    float lz = m + __logf(bc);
    if (row == CN)
        ((float4*)g_startlp)[t] = make_float4(v.x - lz, v.y - lz, v.z - lz, v.w - lz);
    else if (t == 0)
        g_rowlz[row] = lz;
}

// ---------------------------------------------------------------------------
// term sparse stage: one block per TWO words (grid VN/2). 8 warps; warp w
// computes the pair logits for k=w of word0 and word1 (4 independent uint4
// loads in flight per lane). Dedup'd exp-sums into g_sumb. Logits O(1):
// no max pass needed.
// ---------------------------------------------------------------------------
__global__ __launch_bounds__(256) void term_pair_k(
    const float* __restrict__ tow, const float* __restrict__ tob,
    const int* __restrict__ w2s)
{
    __shared__ float ws[2][HN];
    __shared__ int cs[2][SPW];
    int v0 = blockIdx.x * 2, tid = threadIdx.x;
    {
        int w = tid >> 7, c4 = tid & 127;  // 2 x 128 float4
        ((float4*)ws[w])[c4] = ((const float4*)(tow + (size_t)(v0 + w) * HN))[c4];
    }
    if (tid < 16) cs[tid >> 3][tid & 7] = w2s[v0 * SPW + tid];
    __syncthreads();
    int warp = tid >> 5, lane = tid & 31;
    int c0 = cs[0][warp], c1 = cs[1][warp];
    const uint4* hA = (const uint4*)(g_hpb + (size_t)c0 * HN);
    const uint4* hB = (const uint4*)(g_hpb + (size_t)c1 * HN);
    const float4* w0v = (const float4*)ws[0];
    const float4* w1v = (const float4*)ws[1];
    float s0 = 0.f, s1 = 0.f;
#pragma unroll
    for (int it = 0; it < 2; it++) {
        int idx = it * 32 + lane;
        uint4 qa = hA[idx];
        uint4 qb = hB[idx];
        float4 wa0 = w0v[idx * 2], wa1 = w0v[idx * 2 + 1];
        float4 wb0 = w1v[idx * 2], wb1 = w1v[idx * 2 + 1];
        __nv_bfloat162 p;
        p = *(__nv_bfloat162*)&qa.x; s0 = fmaf(__low2float(p), wa0.x, s0); s0 = fmaf(__high2float(p), wa0.y, s0);
        p = *(__nv_bfloat162*)&qa.y; s0 = fmaf(__low2float(p), wa0.z, s0); s0 = fmaf(__high2float(p), wa0.w, s0);
        p = *(__nv_bfloat162*)&qa.z; s0 = fmaf(__low2float(p), wa1.x, s0); s0 = fmaf(__high2float(p), wa1.y, s0);
        p = *(__nv_bfloat162*)&qa.w; s0 = fmaf(__low2float(p), wa1.z, s0); s0 = fmaf(__high2float(p), wa1.w, s0);
        p = *(__nv_bfloat162*)&qb.x; s1 = fmaf(__low2float(p), wb0.x, s1); s1 = fmaf(__high2float(p), wb0.y, s1);
        p = *(__nv_bfloat162*)&qb.y; s1 = fmaf(__low2float(p), wb0.z, s1); s1 = fmaf(__high2float(p), wb0.w, s1);
        p = *(__nv_bfloat162*)&qb.z; s1 = fmaf(__low2float(p), wb1.x, s1); s1 = fmaf(__high2float(p), wb1.y, s1);
        p = *(__nv_bfloat162*)&qb.w; s1 = fmaf(__low2float(p), wb1.z, s1); s1 = fmaf(__high2float(p), wb1.w, s1);
    }
#pragma unroll
    for (int o = 16; o; o >>= 1) {
        s0 += __shfl_xor_sync(0xffffffffu, s0, o);
        s1 += __shfl_xor_sync(0xffffffffu, s1, o);
    }
    if (lane == 0) {
        float l0 = s0 + tob[v0];
        float l1 = s1 + tob[v0 + 1];
        g_pair[v0 * SPW + warp] = l0;
        g_pair[(v0 + 1) * SPW + warp] = l1;
        bool d0 = false, d1 = false;
        for (int k2 = 0; k2 < warp; k2++) {
            if (cs[0][k2] == c0) d0 = true;
            if (cs[1][k2] == c1) d1 = true;
        }
        if (!d0) atomicAdd(&g_sumb[c0], __expf(l0));
        if (!d1) atomicAdd(&g_sumb[c1], __expf(l1));
    }
}

// ---------------------------------------------------------------------------
// fused parallel scan: grid (NCHUNK, BN), 64 threads. Gathers + folds 17
// step matrices per block; manual grid sync; blocks (0,b) finish batch b;
// block (0,0) writes out.
// ---------------------------------------------------------------------------
__global__ __launch_bounds__(64) void scan_all_k(
    const int* __restrict__ text, const int* __restrict__ w2s,
    float* __restrict__ out)
{
    __shared__ int sw[CLEN + 1];
    __shared__ int sws[CLEN + 1][8];
    __shared__ float emi[CLEN + 1][8];
    __shared__ float rlz[CLEN + 1][8];
    __shared__ float bufA[64], bufB[64], sM[64];

    int c = blockIdx.x, b = blockIdx.y, tid = threadIdx.x;
    int base = b * TN + c * CLEN;

    if (tid < CLEN + 1) sw[tid] = text[base + tid];
    __syncthreads();
    for (int idx = tid; idx < (CLEN + 1) * 8; idx += 64) {
        int s = idx >> 3, j = idx & 7;
        int st = w2s[sw[s] * 8 + j];
        sws[s][j] = st;
        rlz[s][j] = g_rowlz[st];
        if (s >= 1) emi[s][j] = g_pair[sw[s] * 8 + j] - __logf(g_sumb[st]);
    }
    __syncthreads();

    int j = tid >> 3, i = tid & 7;
    float* cur = bufA;
    float* nxt = bufB;
    cur[tid] = g_trans[(size_t)sws[0][i] * CN + sws[1][j]] - rlz[0][i] + emi[1][j];
    float pend = g_trans[(size_t)sws[1][i] * CN + sws[2][j]] - rlz[1][i] + emi[2][j];
    __syncthreads();

    for (int s = 1; s < CLEN; s++) {
        sM[tid] = pend;
        if (s + 1 < CLEN)
            pend = g_trans[(size_t)sws[s + 1][i] * CN + sws[s + 2][j]]
                   - rlz[s + 1][i] + emi[s + 2][j];
        __syncthreads();
        const float* Mr = &sM[j << 3];
        float v0 = Mr[0] + cur[0 * 8 + i];
        float v1 = Mr[1] + cur[1 * 8 + i];
        float v2 = Mr[2] + cur[2 * 8 + i];
        float v3 = Mr[3] + cur[3 * 8 + i];
        float v4 = Mr[4] + cur[4 * 8 + i];
        float v5 = Mr[5] + cur[5 * 8 + i];
        float v6 = Mr[6] + cur[6 * 8 + i];
        float v7 = Mr[7] + cur[7 * 8 + i];
        float m = fmaxf(fmaxf(fmaxf(v0, v1), fmaxf(v2, v3)),
                        fmaxf(fmaxf(v4, v5), fmaxf(v6, v7)));
        float sum = ((__expf(v0 - m) + __expf(v1 - m)) + (__expf(v2 - m) + __expf(v3 - m))) +
                    ((__expf(v4 - m) + __expf(v5 - m)) + (__expf(v6 - m) + __expf(v7 - m)));
        nxt[tid] = m + __logf(sum);
        __syncthreads();
        float* tp = cur; cur = nxt; nxt = tp;
    }
    g_chunk[((size_t)b * NCHUNK + c) * 64 + tid] = cur[tid];
    __threadfence();
    __syncthreads();
    if (tid == 0) atomicAdd(&g_cnt1, 1u);
    if (c != 0) return;

    // ---- finisher for batch b ----
    if (tid == 0) {
        while (atomicAdd(&g_cnt1, 0u) < (unsigned)(NCHUNK * BN)) __nanosleep(64);
    }
    __syncthreads();
    __threadfence();

    if (tid < 8) {
        int c0 = sws[0][tid];
        float an = g_startlp[c0] + g_pair[sw[0] * 8 + tid] - __logf(g_sumb[c0]);
        float a[8];
#pragma unroll
        for (int q = 0; q < 8; q++) a[q] = __shfl_sync(0xFFu, an, q);
        for (int cc = 0; cc < NCHUNK; cc++) {
            const float4* p4 =
                (const float4*)(g_chunk + ((size_t)b * NCHUNK + cc) * 64 + (tid << 3));
            float4 pA = p4[0], pB = p4[1];
            float v0 = pA.x + a[0], v1 = pA.y + a[1], v2 = pA.z + a[2], v3 = pA.w + a[3];
            float v4 = pB.x + a[4], v5 = pB.y + a[5], v6 = pB.z + a[6], v7 = pB.w + a[7];
            float m = fmaxf(fmaxf(fmaxf(v0, v1), fmaxf(v2, v3)),
                            fmaxf(fmaxf(v4, v5), fmaxf(v6, v7)));
            float s = ((__expf(v0 - m) + __expf(v1 - m)) + (__expf(v2 - m) + __expf(v3 - m))) +
                      ((__expf(v4 - m) + __expf(v5 - m)) + (__expf(v6 - m) + __expf(v7 - m)));
            an = m + __logf(s);
#pragma unroll
            for (int q = 0; q < 8; q++) a[q] = __shfl_sync(0xFFu, an, q);
        }
        if (tid == 0) {
            float m = a[0];
#pragma unroll
            for (int q = 1; q < 8; q++) m = fmaxf(m, a[q]);
            float s = 0.f;
#pragma unroll
            for (int q = 0; q < 8; q++) s += __expf(a[q] - m);
            g_ev[b] = m + __logf(s);
            __threadfence();
            atomicAdd(&g_cnt2, 1u);
        }
    }
    if (b != 0) return;

    if (tid == 0) {
        while (atomicAdd(&g_cnt2, 0u) < (unsigned)BN) __nanosleep(64);
        __threadfence();
        float s = 0.f;
#pragma unroll
        for (int q = 0; q < BN; q++) s += g_ev[q];
        out[0] = s;
    }
}

// ---------------------------------------------------------------------------
extern "C" void kernel_launch(void* const* d_in, const int* in_sizes, int n_in,
                              void* d_out, int out_size)
{
    const float* start_emb = (const float*)d_in[0];
    const float* start_l1w = (const float*)d_in[1];
    const float* start_l1b = (const float*)d_in[2];
    const float* start_l2w = (const float*)d_in[3];
    const float* start_l2b = (const float*)d_in[4];
    const float* start_ow  = (const float*)d_in[5];
    const float* start_ob  = (const float*)d_in[6];
    const float* state_emb = (const float*)d_in[7];
    const float* trans_l1w = (const float*)d_in[8];
    const float* trans_l1b = (const float*)d_in[9];
    const float* trans_l2w = (const float*)d_in[10];
    const float* trans_l2b = (const float*)d_in[11];
    const float* proj_w    = (const float*)d_in[12];
    const float* pret_emb  = (const float*)d_in[13];
    const float* term_l1w  = (const float*)d_in[14];
    const float* term_l1b  = (const float*)d_in[15];
    const float* term_l2w  = (const float*)d_in[16];
    const float* term_l2b  = (const float*)d_in[17];
    const float* term_ow   = (const float*)d_in[18];
    const float* term_ob   = (const float*)d_in[19];
    const int*   text      = (const int*)d_in[20];
    const int*   w2s       = (const int*)d_in[21];
    float* out = (float*)d_out;

    // one-time infra (no device memory): low-priority side stream + events
    static cudaStream_t s1 = nullptr;
    static cudaEvent_t evA = nullptr, evB = nullptr;
    if (s1 == nullptr) {
        int loPri = 0, hiPri = 0;
        cudaDeviceGetStreamPriorityRange(&loPri, &hiPri);
        cudaStreamCreateWithPriority(&s1, cudaStreamNonBlocking, loPri);
        cudaEventCreateWithFlags(&evA, cudaEventDisableTiming);
        cudaEventCreateWithFlags(&evB, cudaEventDisableTiming);
    }
    cudaStream_t s0 = (cudaStream_t)0;  // legacy stream (what the harness captures)

    // 1) layer-1 GEMMs (3 chains, z-batched) + scratch init
    gemm_l1_k<<<dim3(HN / 64, CN / 64, 3), 128, 0, s0>>>(
        start_emb, state_emb, pret_emb,
        start_l1w, trans_l1w, term_l1w,
        start_l1b, trans_l1b, term_l1b,
        start_ob);
    // 2) layer-2 GEMMs (start head fused via atomics)
    gemm_l2_k<<<dim3(HN / 64, CN / 64, 3), 128, 0, s0>>>(
        start_l2w, trans_l2w, term_l2w,
        start_l2b, trans_l2b, term_l2b,
        start_emb, state_emb, pret_emb,
        start_ow);
    cudaEventRecord(evA, s0);

    // 3) SMALL kernels issued FIRST so they grab SMs; the huge term grid
    //    backfills around them on the low-priority stream.
    gemm_proj_k<<<dim3(CN / 64, CN / 64, 1), 128, 0, s0>>>(proj_w);
    rowlse_k<<<CN + 1, 256, 0, s0>>>();

    // term stage: depends only on l2; runs concurrently with proj + rowlse
    cudaStreamWaitEvent(s1, evA, 0);
    term_pair_k<<<VN / 2, 256, 0, s1>>>(term_ow, term_ob, w2s);
    cudaEventRecord(evB, s1);

    // join, then 4) fused parallel scan + final evidence
    cudaStreamWaitEvent(s0, evB, 0);
    scan_all_k<<<dim3(NCHUNK, BN), 64, 0, s0>>>(text, w2s, out);
}

// round 9
// speedup vs baseline: 2.7802x; 1.0184x over previous
#include <cuda_runtime.h>
#include <cuda_bf16.h>
#include <math.h>

#define CN 1024
#define HN 512
#define VN 32000
#define BN 16
#define TN 256
#define SPW 8
#define NCHUNK 15
#define CLEN 17   // 15*17 = 255 step matrices

// ------------------------- scratch (static device memory; no allocs) -------
__device__ __nv_bfloat16 g_tmpb[3 * CN * HN];  // relu(layer1) per chain, bf16
__device__ __nv_bfloat16 g_htb[CN * HN];       // trans residual out (bf16)
__device__ unsigned char g_hp8[CN * HN];       // term residual out (fp8 e4m3)
__device__ float g_sl[CN];                     // start logits (bias + fused head dots)
__device__ float g_slse;                       // lse of start logits
__device__ float g_trans[CN * CN];             // raw trans logits
__device__ float g_rowsum[CN];                 // per-row sum(exp(trans)) (no max; safe)
__device__ float g_pair[VN * SPW];             // term pair logits
__device__ float g_sumb[CN];                   // sum exp(logit) per state
__device__ float g_chunk[BN * NCHUNK * 64];    // chunk products
__device__ float g_ev[BN];
__device__ unsigned g_cnt1;
__device__ unsigned g_cnt2;

// fp8 helpers ---------------------------------------------------------------
__device__ __forceinline__ float4 fp8x4_to_f4(unsigned w) {
    unsigned lo, hi;
    asm("cvt.rn.f16x2.e4m3x2 %0, %1;" : "=r"(lo) : "h"((unsigned short)(w & 0xffffu)));
    asm("cvt.rn.f16x2.e4m3x2 %0, %1;" : "=r"(hi) : "h"((unsigned short)(w >> 16)));
    __half2 h0 = *(__half2*)&lo, h1 = *(__half2*)&hi;
    float2 f0 = __half22float2(h0), f1 = __half22float2(h1);
    return make_float4(f0.x, f0.y, f1.x, f1.y);
}
__device__ __forceinline__ unsigned short f2_to_fp8x2(float v0, float v1) {
    unsigned short u;  // lo byte = v0, hi byte = v1
    asm("cvt.rn.satfinite.e4m3x2.f32 %0, %1, %2;" : "=h"(u) : "f"(v1), "f"(v0));
    return u;
}

// ---------------------------------------------------------------------------
// bf16 tensor-core GEMM core (R4-proven): CTA 64x64, 128 threads, 2x2 warps,
// warp tile 32x32, K-step 32, register-prefetch, manual LDS fragment loads.
// Fused epilogues: headw (row-dot -> atomicAdd g_sl), rowsum (atomicAdd
// per-row sum of expf(out)), out8 (fp8 store).
// ---------------------------------------------------------------------------
__device__ __forceinline__ void mma16816(float* d, const unsigned* a, const unsigned* b) {
    asm volatile(
        "mma.sync.aligned.m16n8k16.row.col.f32.bf16.bf16.f32 "
        "{%0,%1,%2,%3}, {%4,%5,%6,%7}, {%8,%9}, {%0,%1,%2,%3};\n"
        : "+f"(d[0]), "+f"(d[1]), "+f"(d[2]), "+f"(d[3])
        : "r"(a[0]), "r"(a[1]), "r"(a[2]), "r"(a[3]), "r"(b[0]), "r"(b[1]));
}

#define SSTRIDE 40  // bf16 elems per smem row (80B) -> conflict-free frag loads

template <bool ABF>
__device__ __forceinline__ void gemm_core(
    const float* __restrict__ Af, const __nv_bfloat16* __restrict__ Ab,
    const float* __restrict__ W, const float* __restrict__ bias,
    const float* __restrict__ res, float* __restrict__ outF,
    __nv_bfloat16* __restrict__ outB, unsigned char* __restrict__ out8,
    const float* __restrict__ headw, float* __restrict__ rowsum,
    int N, int K, int relu)
{
    __shared__ __nv_bfloat16 sA[64 * SSTRIDE];
    __shared__ __nv_bfloat16 sB[64 * SSTRIDE];

    const int t = threadIdx.x;
    const int lane = t & 31, warp = t >> 5;
    const int wm = warp >> 1, wn = warp & 1;
    const int row0 = blockIdx.y * 64, col0 = blockIdx.x * 64;
    const int lr = lane >> 2, lc = lane & 3;

    float acc[2][4][4];
#pragma unroll
    for (int mt = 0; mt < 2; mt++)
#pragma unroll
        for (int nt = 0; nt < 4; nt++)
#pragma unroll
            for (int q = 0; q < 4; q++) acc[mt][nt][q] = 0.f;

    float4 pa[4];
    uint2 pab[4];
    float4 pw[4];

#pragma unroll
    for (int i = 0; i < 4; i++) {
        int id = i * 128 + t, r = id >> 3, c4 = id & 7;
        if (ABF)
            pab[i] = *(const uint2*)(Ab + (size_t)(row0 + r) * K + c4 * 4);
        else
            pa[i] = *(const float4*)(Af + (size_t)(row0 + r) * K + c4 * 4);
        pw[i] = *(const float4*)(W + (size_t)(col0 + r) * K + c4 * 4);
    }

    const int NT = K / 32;
    for (int kt = 0; kt < NT; kt++) {
#pragma unroll
        for (int i = 0; i < 4; i++) {
            int id = i * 128 + t, r = id >> 3, c4 = id & 7;
            __nv_bfloat16* da = &sA[r * SSTRIDE + c4 * 4];
            if (ABF) {
                *(unsigned*)da = pab[i].x;
                *(unsigned*)(da + 2) = pab[i].y;
            } else {
                *(__nv_bfloat162*)da = __float22bfloat162_rn(make_float2(pa[i].x, pa[i].y));
                *(__nv_bfloat162*)(da + 2) = __float22bfloat162_rn(make_float2(pa[i].z, pa[i].w));
            }
            __nv_bfloat16* dw = &sB[r * SSTRIDE + c4 * 4];
            *(__nv_bfloat162*)dw = __float22bfloat162_rn(make_float2(pw[i].x, pw[i].y));
            *(__nv_bfloat162*)(dw + 2) = __float22bfloat162_rn(make_float2(pw[i].z, pw[i].w));
        }
        __syncthreads();

        int kn = (kt + 1) * 32;
        if (kn < K) {
#pragma unroll
            for (int i = 0; i < 4; i++) {
                int id = i * 128 + t, r = id >> 3, c4 = id & 7;
                if (ABF)
                    pab[i] = *(const uint2*)(Ab + (size_t)(row0 + r) * K + kn + c4 * 4);
                else
                    pa[i] = *(const float4*)(Af + (size_t)(row0 + r) * K + kn + c4 * 4);
                pw[i] = *(const float4*)(W + (size_t)(col0 + r) * K + kn + c4 * 4);
            }
        }

#pragma unroll
        for (int kk = 0; kk < 2; kk++) {
            unsigned af[2][4], bfr[4][2];
            int kb = kk * 16 + lc * 2;
#pragma unroll
            for (int mt = 0; mt < 2; mt++) {
                const __nv_bfloat16* p = &sA[(wm * 32 + mt * 16 + lr) * SSTRIDE + kb];
                af[mt][0] = *(const unsigned*)p;
                af[mt][1] = *(const unsigned*)(p + 8 * SSTRIDE);
                af[mt][2] = *(const unsigned*)(p + 8);
                af[mt][3] = *(const unsigned*)(p + 8 * SSTRIDE + 8);
            }
#pragma unroll
            for (int nt = 0; nt < 4; nt++) {
                const __nv_bfloat16* p = &sB[(wn * 32 + nt * 8 + lr) * SSTRIDE + kb];
                bfr[nt][0] = *(const unsigned*)p;
                bfr[nt][1] = *(const unsigned*)(p + 8);
            }
#pragma unroll
            for (int mt = 0; mt < 2; mt++)
#pragma unroll
                for (int nt = 0; nt < 4; nt++) mma16816(acc[mt][nt], af[mt], bfr[nt]);
        }
        __syncthreads();
    }

    float part[2][2] = {{0.f, 0.f}, {0.f, 0.f}};
    float rs[2][2] = {{0.f, 0.f}, {0.f, 0.f}};
#pragma unroll
    for (int mt = 0; mt < 2; mt++)
#pragma unroll
        for (int nt = 0; nt < 4; nt++) {
            int gr = row0 + wm * 32 + mt * 16 + lr;
            int gc = col0 + wn * 32 + nt * 8 + lc * 2;
            float2 b2 = make_float2(0.f, 0.f);
            if (bias) b2 = *(const float2*)(bias + gc);
#pragma unroll
            for (int h = 0; h < 2; h++) {
                int r_ = gr + h * 8;
                float v0 = acc[mt][nt][h * 2 + 0] + b2.x;
                float v1 = acc[mt][nt][h * 2 + 1] + b2.y;
                if (relu) { v0 = fmaxf(v0, 0.f); v1 = fmaxf(v1, 0.f); }
                if (res) {
                    float2 r2 = *(const float2*)(res + (size_t)r_ * N + gc);
                    v0 += r2.x; v1 += r2.y;
                }
                if (headw) {
                    float2 wv = *(const float2*)(headw + gc);
                    part[mt][h] = fmaf(v0, wv.x, fmaf(v1, wv.y, part[mt][h]));
                }
                if (rowsum) rs[mt][h] += __expf(v0) + __expf(v1);
                if (outF) *(float2*)(outF + (size_t)r_ * N + gc) = make_float2(v0, v1);
                if (outB)
                    *(__nv_bfloat162*)(outB + (size_t)r_ * N + gc) =
                        __float22bfloat162_rn(make_float2(v0, v1));
                if (out8)
                    *(unsigned short*)(out8 + (size_t)r_ * N + gc) = f2_to_fp8x2(v0, v1);
            }
        }
    if (headw || rowsum) {
#pragma unroll
        for (int mt = 0; mt < 2; mt++)
#pragma unroll
            for (int h = 0; h < 2; h++) {
                float p = headw ? part[mt][h] : rs[mt][h];
                p += __shfl_xor_sync(0xffffffffu, p, 1);
                p += __shfl_xor_sync(0xffffffffu, p, 2);
                if (lc == 0) {
                    int r_ = row0 + wm * 32 + mt * 16 + lr + h * 8;
                    atomicAdd(headw ? &g_sl[r_] : &rowsum[r_], p);
                }
            }
    }
}

// layer 1 (batched over z=3 chains). Block (0,0,0) also initializes scratch.
__global__ __launch_bounds__(128) void gemm_l1_k(
    const float* A0, const float* A1, const float* A2,
    const float* W0, const float* W1, const float* W2,
    const float* B0, const float* B1, const float* B2,
    const float* ob)
{
    int z = blockIdx.z;
    if (z == 0 && blockIdx.x == 0 && blockIdx.y == 0) {
        float ob0 = ob[0];
        for (int i = threadIdx.x; i < CN; i += 128) {
            g_sl[i] = ob0;
            g_sumb[i] = 0.f;
            g_rowsum[i] = 0.f;
        }
        if (threadIdx.x == 0) { g_cnt1 = 0u; g_cnt2 = 0u; }
    }
    const float* A = z == 0 ? A0 : (z == 1 ? A1 : A2);
    const float* W = z == 0 ? W0 : (z == 1 ? W1 : W2);
    const float* B = z == 0 ? B0 : (z == 1 ? B1 : B2);
    gemm_core<false>(A, nullptr, W, B, nullptr, nullptr,
                     g_tmpb + (size_t)z * CN * HN, nullptr, nullptr, nullptr,
                     HN, HN, 1);
}

// layer 2 (batched). z0: head-fused (no store). z1 -> g_htb. z2 -> g_hp8.
__global__ __launch_bounds__(128) void gemm_l2_k(
    const float* W0, const float* W1, const float* W2,
    const float* B0, const float* B1, const float* B2,
    const float* R0, const float* R1, const float* R2,
    const float* ow)
{
    int z = blockIdx.z;
    const float* W = z == 0 ? W0 : (z == 1 ? W1 : W2);
    const float* B = z == 0 ? B0 : (z == 1 ? B1 : B2);
    const float* R = z == 0 ? R0 : (z == 1 ? R1 : R2);
    __nv_bfloat16* oB = z == 1 ? g_htb : nullptr;
    unsigned char* o8 = z == 2 ? g_hp8 : nullptr;
    const float* hw = z == 0 ? ow : nullptr;
    gemm_core<true>(nullptr, g_tmpb + (size_t)z * CN * HN, W, B, R, nullptr, oB, o8,
                    hw, nullptr, HN, HN, 1);
}

// trans projection: g_trans = g_htb @ proj_w^T, fused row exp-sums.
__global__ __launch_bounds__(128) void gemm_proj_k(const float* W)
{
    gemm_core<true>(nullptr, g_htb, W, nullptr, nullptr, g_trans, nullptr, nullptr,
                    nullptr, g_rowsum, CN, HN, 0);
}

// ---------------------------------------------------------------------------
// term sparse stage: one block per TWO words. 8 warps; warp w computes the
// pair logits for k=w of word0 and word1, reading fp8 hp rows (512B each).
// Dedup'd exp-sums into g_sumb. Logits O(1): no max pass needed.
// ---------------------------------------------------------------------------
__global__ __launch_bounds__(256) void term_pair_k(
    const float* __restrict__ tow, const float* __restrict__ tob,
    const int* __restrict__ w2s)
{
    __shared__ float ws[2][HN];
    __shared__ int cs[2][SPW];
    int v0 = blockIdx.x * 2, tid = threadIdx.x;
    {
        int w = tid >> 7, c4 = tid & 127;  // 2 x 128 float4
        ((float4*)ws[w])[c4] = ((const float4*)(tow + (size_t)(v0 + w) * HN))[c4];
    }
    if (tid < 16) cs[tid >> 3][tid & 7] = w2s[v0 * SPW + tid];
    __syncthreads();
    int warp = tid >> 5, lane = tid & 31;
    int c0 = cs[0][warp], c1 = cs[1][warp];
    const uint2* hA = (const uint2*)(g_hp8 + (size_t)c0 * HN);
    const uint2* hB = (const uint2*)(g_hp8 + (size_t)c1 * HN);
    const float4* w0v = (const float4*)ws[0];
    const float4* w1v = (const float4*)ws[1];
    float s0 = 0.f, s1 = 0.f;
#pragma unroll
    for (int it = 0; it < 2; it++) {
        int idx = it * 32 + lane;
        uint2 qa = hA[idx];
        uint2 qb = hB[idx];
        float4 a0 = fp8x4_to_f4(qa.x), a1 = fp8x4_to_f4(qa.y);
        float4 b0 = fp8x4_to_f4(qb.x), b1 = fp8x4_to_f4(qb.y);
        float4 wa0 = w0v[idx * 2], wa1 = w0v[idx * 2 + 1];
        float4 wb0 = w1v[idx * 2], wb1 = w1v[idx * 2 + 1];
        s0 = fmaf(a0.x, wa0.x, s0); s0 = fmaf(a0.y, wa0.y, s0);
        s0 = fmaf(a0.z, wa0.z, s0); s0 = fmaf(a0.w, wa0.w, s0);
        s0 = fmaf(a1.x, wa1.x, s0); s0 = fmaf(a1.y, wa1.y, s0);
        s0 = fmaf(a1.z, wa1.z, s0); s0 = fmaf(a1.w, wa1.w, s0);
        s1 = fmaf(b0.x, wb0.x, s1); s1 = fmaf(b0.y, wb0.y, s1);
        s1 = fmaf(b0.z, wb0.z, s1); s1 = fmaf(b0.w, wb0.w, s1);
        s1 = fmaf(b1.x, wb1.x, s1); s1 = fmaf(b1.y, wb1.y, s1);
        s1 = fmaf(b1.z, wb1.z, s1); s1 = fmaf(b1.w, wb1.w, s1);
    }
#pragma unroll
    for (int o = 16; o; o >>= 1) {
        s0 += __shfl_xor_sync(0xffffffffu, s0, o);
        s1 += __shfl_xor_sync(0xffffffffu, s1, o);
    }
    if (lane == 0) {
        float l0 = s0 + tob[v0];
        float l1 = s1 + tob[v0 + 1];
        g_pair[v0 * SPW + warp] = l0;
        g_pair[(v0 + 1) * SPW + warp] = l1;
        bool d0 = false, d1 = false;
        for (int k2 = 0; k2 < warp; k2++) {
            if (cs[0][k2] == c0) d0 = true;
            if (cs[1][k2] == c1) d1 = true;
        }
        if (!d0) atomicAdd(&g_sumb[c0], __expf(l0));
        if (!d1) atomicAdd(&g_sumb[c1], __expf(l1));
    }
}

// ---------------------------------------------------------------------------
// fused parallel scan: grid (NCHUNK, BN), 64 threads. Each thread batch-loads
// its 17 scattered trans entries (MLP 17) into a [17][64] smem stage, then
// folds with 1 sync/step. Manual grid sync; blocks (0,b) finish batch b;
// block (1,0) computes the start-lse pre-sync; block (0,0) writes out.
// ---------------------------------------------------------------------------
__global__ __launch_bounds__(64) void scan_all_k(
    const int* __restrict__ text, const int* __restrict__ w2s,
    float* __restrict__ out)
{
    __shared__ int sw[CLEN + 1];
    __shared__ int sws[CLEN + 1][8];
    __shared__ float emi[CLEN + 1][8];
    __shared__ float rlz[CLEN + 1][8];
    __shared__ float sMall[CLEN][64];
    __shared__ float bufA[64], bufB[64];
    __shared__ float red2[2];

    int c = blockIdx.x, b = blockIdx.y, tid = threadIdx.x;
    int base = b * TN + c * CLEN;

    if (tid < CLEN + 1) sw[tid] = text[base + tid];
    __syncthreads();
    for (int idx = tid; idx < (CLEN + 1) * 8; idx += 64) {
        int s = idx >> 3, j = idx & 7;
        int st = w2s[sw[s] * 8 + j];
        sws[s][j] = st;
        rlz[s][j] = __logf(g_rowsum[st]);
        if (s >= 1) emi[s][j] = g_pair[sw[s] * 8 + j] - __logf(g_sumb[st]);
    }
    __syncthreads();

    int j = tid >> 3, i = tid & 7;
    // gather all 17 step-matrix entries for this thread — fully parallel loads
#pragma unroll
    for (int s = 0; s < CLEN; s++)
        sMall[s][tid] = g_trans[(size_t)sws[s][i] * CN + sws[s + 1][j]]
                        - rlz[s][i] + emi[s + 1][j];
    __syncthreads();

    float* cur = &sMall[0][0];
    float* nxt = bufA;
    float* spare = bufB;
    for (int s = 1; s < CLEN; s++) {
        const float* Mr = &sMall[s][j << 3];
        float v0 = Mr[0] + cur[0 * 8 + i];
        float v1 = Mr[1] + cur[1 * 8 + i];
        float v2 = Mr[2] + cur[2 * 8 + i];
        float v3 = Mr[3] + cur[3 * 8 + i];
        float v4 = Mr[4] + cur[4 * 8 + i];
        float v5 = Mr[5] + cur[5 * 8 + i];
        float v6 = Mr[6] + cur[6 * 8 + i];
        float v7 = Mr[7] + cur[7 * 8 + i];
        float m = fmaxf(fmaxf(fmaxf(v0, v1), fmaxf(v2, v3)),
                        fmaxf(fmaxf(v4, v5), fmaxf(v6, v7)));
        float sum = ((__expf(v0 - m) + __expf(v1 - m)) + (__expf(v2 - m) + __expf(v3 - m))) +
                    ((__expf(v4 - m) + __expf(v5 - m)) + (__expf(v6 - m) + __expf(v7 - m)));
        nxt[tid] = m + __logf(sum);
        __syncthreads();
        float* old = (s == 1) ? spare : cur;
        cur = nxt;
        nxt = old;
    }
    g_chunk[((size_t)b * NCHUNK + c) * 64 + tid] = cur[tid];
    __threadfence();
    __syncthreads();

    // block (1,0): start-lse before arriving at the sync (logits O(1); no max)
    if (c == 1 && b == 0) {
        const float4* sl4 = (const float4*)g_sl;
        float es = 0.f;
#pragma unroll
        for (int q = 0; q < 4; q++) {
            float4 v = sl4[tid * 4 + q];
            es += __expf(v.x) + __expf(v.y) + __expf(v.z) + __expf(v.w);
        }
#pragma unroll
        for (int o = 16; o; o >>= 1) es += __shfl_xor_sync(0xffffffffu, es, o);
        if ((tid & 31) == 0) red2[tid >> 5] = es;
        __syncthreads();
        if (tid == 0) {
            g_slse = __logf(red2[0] + red2[1]);
            __threadfence();
        }
        __syncthreads();
    }
    if (tid == 0) atomicAdd(&g_cnt1, 1u);
    if (c != 0) return;

    // ---- finisher for batch b ----
    if (tid == 0) {
        while (atomicAdd(&g_cnt1, 0u) < (unsigned)(NCHUNK * BN)) __nanosleep(64);
    }
    __syncthreads();
    __threadfence();

    if (tid < 8) {
        int c0 = sws[0][tid];
        float an = g_sl[c0] - g_slse + g_pair[sw[0] * 8 + tid] - __logf(g_sumb[c0]);
        float a[8];
#pragma unroll
        for (int q = 0; q < 8; q++) a[q] = __shfl_sync(0xFFu, an, q);
        for (int cc = 0; cc < NCHUNK; cc++) {
            const float4* p4 =
                (const float4*)(g_chunk + ((size_t)b * NCHUNK + cc) * 64 + (tid << 3));
            float4 pA = p4[0], pB = p4[1];
            float v0 = pA.x + a[0], v1 = pA.y + a[1], v2 = pA.z + a[2], v3 = pA.w + a[3];
            float v4 = pB.x + a[4], v5 = pB.y + a[5], v6 = pB.z + a[6], v7 = pB.w + a[7];
            float m = fmaxf(fmaxf(fmaxf(v0, v1), fmaxf(v2, v3)),
                            fmaxf(fmaxf(v4, v5), fmaxf(v6, v7)));
            float s = ((__expf(v0 - m) + __expf(v1 - m)) + (__expf(v2 - m) + __expf(v3 - m))) +
                      ((__expf(v4 - m) + __expf(v5 - m)) + (__expf(v6 - m) + __expf(v7 - m)));
            an = m + __logf(s);
#pragma unroll
            for (int q = 0; q < 8; q++) a[q] = __shfl_sync(0xFFu, an, q);
        }
        if (tid == 0) {
            float m = a[0];
#pragma unroll
            for (int q = 1; q < 8; q++) m = fmaxf(m, a[q]);
            float s = 0.f;
#pragma unroll
            for (int q = 0; q < 8; q++) s += __expf(a[q] - m);
            g_ev[b] = m + __logf(s);
            __threadfence();
            atomicAdd(&g_cnt2, 1u);
        }
    }
    if (b != 0) return;

    if (tid == 0) {
        while (atomicAdd(&g_cnt2, 0u) < (unsigned)BN) __nanosleep(64);
        __threadfence();
        float s = 0.f;
#pragma unroll
        for (int q = 0; q < BN; q++) s += g_ev[q];
        out[0] = s;
    }
}

// ---------------------------------------------------------------------------
extern "C" void kernel_launch(void* const* d_in, const int* in_sizes, int n_in,
                              void* d_out, int out_size)
{
    const float* start_emb = (const float*)d_in[0];
    const float* start_l1w = (const float*)d_in[1];
    const float* start_l1b = (const float*)d_in[2];
    const float* start_l2w = (const float*)d_in[3];
    const float* start_l2b = (const float*)d_in[4];
    const float* start_ow  = (const float*)d_in[5];
    const float* start_ob  = (const float*)d_in[6];
    const float* state_emb = (const float*)d_in[7];
    const float* trans_l1w = (const float*)d_in[8];
    const float* trans_l1b = (const float*)d_in[9];
    const float* trans_l2w = (const float*)d_in[10];
    const float* trans_l2b = (const float*)d_in[11];
    const float* proj_w    = (const float*)d_in[12];
    const float* pret_emb  = (const float*)d_in[13];
    const float* term_l1w  = (const float*)d_in[14];
    const float* term_l1b  = (const float*)d_in[15];
    const float* term_l2w  = (const float*)d_in[16];
    const float* term_l2b  = (const float*)d_in[17];
    const float* term_ow   = (const float*)d_in[18];
    const float* term_ob   = (const float*)d_in[19];
    const int*   text      = (const int*)d_in[20];
    const int*   w2s       = (const int*)d_in[21];
    float* out = (float*)d_out;

    // one-time infra (no device memory): low-priority side stream + events
    static cudaStream_t s1 = nullptr;
    static cudaEvent_t evA = nullptr, evB = nullptr;
    if (s1 == nullptr) {
        int loPri = 0, hiPri = 0;
        cudaDeviceGetStreamPriorityRange(&loPri, &hiPri);
        cudaStreamCreateWithPriority(&s1, cudaStreamNonBlocking, loPri);
        cudaEventCreateWithFlags(&evA, cudaEventDisableTiming);
        cudaEventCreateWithFlags(&evB, cudaEventDisableTiming);
    }
    cudaStream_t s0 = (cudaStream_t)0;  // legacy stream (what the harness captures)

    // 1) layer-1 GEMMs (3 chains, z-batched) + scratch init
    gemm_l1_k<<<dim3(HN / 64, CN / 64, 3), 128, 0, s0>>>(
        start_emb, state_emb, pret_emb,
        start_l1w, trans_l1w, term_l1w,
        start_l1b, trans_l1b, term_l1b,
        start_ob);
    // 2) layer-2 GEMMs (start head fused via atomics; term out in fp8)
    gemm_l2_k<<<dim3(HN / 64, CN / 64, 3), 128, 0, s0>>>(
        start_l2w, trans_l2w, term_l2w,
        start_l2b, trans_l2b, term_l2b,
        start_emb, state_emb, pret_emb,
        start_ow);
    cudaEventRecord(evA, s0);

    // 3) proj (with fused row exp-sums) issued FIRST; the huge term grid
    //    backfills around it on the low-priority stream.
    gemm_proj_k<<<dim3(CN / 64, CN / 64, 1), 128, 0, s0>>>(proj_w);

    cudaStreamWaitEvent(s1, evA, 0);
    term_pair_k<<<VN / 2, 256, 0, s1>>>(term_ow, term_ob, w2s);
    cudaEventRecord(evB, s1);

    // join, then 4) fused parallel scan + final evidence
    cudaStreamWaitEvent(s0, evB, 0);
    scan_all_k<<<dim3(NCHUNK, BN), 64, 0, s0>>>(text, w2s, out);
}

// round 10
// speedup vs baseline: 3.5686x; 1.2836x over previous
#include <cuda_runtime.h>
#include <cuda_bf16.h>
#include <cuda_fp16.h>
#include <math.h>

#define CN 1024
#define HN 512
#define VN 32000
#define BN 16
#define TN 256
#define SPW 8
#define NCHUNK 15
#define CLEN 17   // 15*17 = 255 step matrices

// ------------------------- scratch (static device memory; no allocs) -------
__device__ __nv_bfloat16 g_tmpb[3 * CN * HN];  // relu(layer1) per chain, bf16
__device__ __nv_bfloat16 g_htb[CN * HN];       // trans residual out (bf16)
__device__ unsigned char g_hp8[CN * HN];       // term residual out (fp8 e4m3)
__device__ float g_sl[CN];                     // start logits (bias + fused head dots)
__device__ float g_slse;                       // lse of start logits
__device__ float g_trans[CN * CN];             // raw trans logits
__device__ float g_rowsum[CN];                 // per-row sum(exp(trans)) (no max; safe)
__device__ float g_pair[VN * SPW];             // term pair logits
__device__ float g_sumb[CN];                   // sum exp(logit) per state
__device__ float g_chunk[BN * NCHUNK * 64];    // chunk products
__device__ float g_ev[BN];
__device__ unsigned g_cnt1;
__device__ unsigned g_cnt2;

// fp8 / half helpers --------------------------------------------------------
__device__ __forceinline__ unsigned fp8x2_to_h2(unsigned short u) {
    unsigned r;
    asm("cvt.rn.f16x2.e4m3x2 %0, %1;" : "=r"(r) : "h"(u));
    return r;
}
__device__ __forceinline__ unsigned h2fma(unsigned a, unsigned b, unsigned c) {
    unsigned d;
    asm("fma.rn.f16x2 %0, %1, %2, %3;" : "=r"(d) : "r"(a), "r"(b), "r"(c));
    return d;
}
__device__ __forceinline__ unsigned short f2_to_fp8x2(float v0, float v1) {
    unsigned short u;  // lo byte = v0, hi byte = v1
    asm("cvt.rn.satfinite.e4m3x2.f32 %0, %1, %2;" : "=h"(u) : "f"(v1), "f"(v0));
    return u;
}

// ---------------------------------------------------------------------------
// bf16 tensor-core GEMM core (R4-proven): CTA 64x64, 128 threads, 2x2 warps,
// warp tile 32x32, K-step 32, register-prefetch, manual LDS fragment loads.
// Fused epilogues: headw (row-dot -> atomicAdd g_sl), rowsum (atomicAdd
// per-row sum of expf(out)), out8 (fp8 store).
// ---------------------------------------------------------------------------
__device__ __forceinline__ void mma16816(float* d, const unsigned* a, const unsigned* b) {
    asm volatile(
        "mma.sync.aligned.m16n8k16.row.col.f32.bf16.bf16.f32 "
        "{%0,%1,%2,%3}, {%4,%5,%6,%7}, {%8,%9}, {%0,%1,%2,%3};\n"
        : "+f"(d[0]), "+f"(d[1]), "+f"(d[2]), "+f"(d[3])
        : "r"(a[0]), "r"(a[1]), "r"(a[2]), "r"(a[3]), "r"(b[0]), "r"(b[1]));
}

#define SSTRIDE 40  // bf16 elems per smem row (80B) -> conflict-free frag loads

template <bool ABF>
__device__ __forceinline__ void gemm_core(
    const float* __restrict__ Af, const __nv_bfloat16* __restrict__ Ab,
    const float* __restrict__ W, const float* __restrict__ bias,
    const float* __restrict__ res, float* __restrict__ outF,
    __nv_bfloat16* __restrict__ outB, unsigned char* __restrict__ out8,
    const float* __restrict__ headw, float* __restrict__ rowsum,
    int N, int K, int relu)
{
    __shared__ __nv_bfloat16 sA[64 * SSTRIDE];
    __shared__ __nv_bfloat16 sB[64 * SSTRIDE];

    const int t = threadIdx.x;
    const int lane = t & 31, warp = t >> 5;
    const int wm = warp >> 1, wn = warp & 1;
    const int row0 = blockIdx.y * 64, col0 = blockIdx.x * 64;
    const int lr = lane >> 2, lc = lane & 3;

    float acc[2][4][4];
#pragma unroll
    for (int mt = 0; mt < 2; mt++)
#pragma unroll
        for (int nt = 0; nt < 4; nt++)
#pragma unroll
            for (int q = 0; q < 4; q++) acc[mt][nt][q] = 0.f;

    float4 pa[4];
    uint2 pab[4];
    float4 pw[4];

#pragma unroll
    for (int i = 0; i < 4; i++) {
        int id = i * 128 + t, r = id >> 3, c4 = id & 7;
        if (ABF)
            pab[i] = *(const uint2*)(Ab + (size_t)(row0 + r) * K + c4 * 4);
        else
            pa[i] = *(const float4*)(Af + (size_t)(row0 + r) * K + c4 * 4);
        pw[i] = *(const float4*)(W + (size_t)(col0 + r) * K + c4 * 4);
    }

    const int NT = K / 32;
    for (int kt = 0; kt < NT; kt++) {
#pragma unroll
        for (int i = 0; i < 4; i++) {
            int id = i * 128 + t, r = id >> 3, c4 = id & 7;
            __nv_bfloat16* da = &sA[r * SSTRIDE + c4 * 4];
            if (ABF) {
                *(unsigned*)da = pab[i].x;
                *(unsigned*)(da + 2) = pab[i].y;
            } else {
                *(__nv_bfloat162*)da = __float22bfloat162_rn(make_float2(pa[i].x, pa[i].y));
                *(__nv_bfloat162*)(da + 2) = __float22bfloat162_rn(make_float2(pa[i].z, pa[i].w));
            }
            __nv_bfloat16* dw = &sB[r * SSTRIDE + c4 * 4];
            *(__nv_bfloat162*)dw = __float22bfloat162_rn(make_float2(pw[i].x, pw[i].y));
            *(__nv_bfloat162*)(dw + 2) = __float22bfloat162_rn(make_float2(pw[i].z, pw[i].w));
        }
        __syncthreads();

        int kn = (kt + 1) * 32;
        if (kn < K) {
#pragma unroll
            for (int i = 0; i < 4; i++) {
                int id = i * 128 + t, r = id >> 3, c4 = id & 7;
                if (ABF)
                    pab[i] = *(const uint2*)(Ab + (size_t)(row0 + r) * K + kn + c4 * 4);
                else
                    pa[i] = *(const float4*)(Af + (size_t)(row0 + r) * K + kn + c4 * 4);
                pw[i] = *(const float4*)(W + (size_t)(col0 + r) * K + kn + c4 * 4);
            }
        }

#pragma unroll
        for (int kk = 0; kk < 2; kk++) {
            unsigned af[2][4], bfr[4][2];
            int kb = kk * 16 + lc * 2;
#pragma unroll
            for (int mt = 0; mt < 2; mt++) {
                const __nv_bfloat16* p = &sA[(wm * 32 + mt * 16 + lr) * SSTRIDE + kb];
                af[mt][0] = *(const unsigned*)p;
                af[mt][1] = *(const unsigned*)(p + 8 * SSTRIDE);
                af[mt][2] = *(const unsigned*)(p + 8);
                af[mt][3] = *(const unsigned*)(p + 8 * SSTRIDE + 8);
            }
#pragma unroll
            for (int nt = 0; nt < 4; nt++) {
                const __nv_bfloat16* p = &sB[(wn * 32 + nt * 8 + lr) * SSTRIDE + kb];
                bfr[nt][0] = *(const unsigned*)p;
                bfr[nt][1] = *(const unsigned*)(p + 8);
            }
#pragma unroll
            for (int mt = 0; mt < 2; mt++)
#pragma unroll
                for (int nt = 0; nt < 4; nt++) mma16816(acc[mt][nt], af[mt], bfr[nt]);
        }
        __syncthreads();
    }

    float part[2][2] = {{0.f, 0.f}, {0.f, 0.f}};
    float rs[2][2] = {{0.f, 0.f}, {0.f, 0.f}};
#pragma unroll
    for (int mt = 0; mt < 2; mt++)
#pragma unroll
        for (int nt = 0; nt < 4; nt++) {
            int gr = row0 + wm * 32 + mt * 16 + lr;
            int gc = col0 + wn * 32 + nt * 8 + lc * 2;
            float2 b2 = make_float2(0.f, 0.f);
            if (bias) b2 = *(const float2*)(bias + gc);
#pragma unroll
            for (int h = 0; h < 2; h++) {
                int r_ = gr + h * 8;
                float v0 = acc[mt][nt][h * 2 + 0] + b2.x;
                float v1 = acc[mt][nt][h * 2 + 1] + b2.y;
                if (relu) { v0 = fmaxf(v0, 0.f); v1 = fmaxf(v1, 0.f); }
                if (res) {
                    float2 r2 = *(const float2*)(res + (size_t)r_ * N + gc);
                    v0 += r2.x; v1 += r2.y;
                }
                if (headw) {
                    float2 wv = *(const float2*)(headw + gc);
                    part[mt][h] = fmaf(v0, wv.x, fmaf(v1, wv.y, part[mt][h]));
                }
                if (rowsum) rs[mt][h] += __expf(v0) + __expf(v1);
                if (outF) *(float2*)(outF + (size_t)r_ * N + gc) = make_float2(v0, v1);
                if (outB)
                    *(__nv_bfloat162*)(outB + (size_t)r_ * N + gc) =
                        __float22bfloat162_rn(make_float2(v0, v1));
                if (out8)
                    *(unsigned short*)(out8 + (size_t)r_ * N + gc) = f2_to_fp8x2(v0, v1);
            }
        }
    if (headw || rowsum) {
#pragma unroll
        for (int mt = 0; mt < 2; mt++)
#pragma unroll
            for (int h = 0; h < 2; h++) {
                float p = headw ? part[mt][h] : rs[mt][h];
                p += __shfl_xor_sync(0xffffffffu, p, 1);
                p += __shfl_xor_sync(0xffffffffu, p, 2);
                if (lc == 0) {
                    int r_ = row0 + wm * 32 + mt * 16 + lr + h * 8;
                    atomicAdd(headw ? &g_sl[r_] : &rowsum[r_], p);
                }
            }
    }
}

// layer 1 (batched over z=3 chains). Block (0,0,0) also initializes scratch.
__global__ __launch_bounds__(128) void gemm_l1_k(
    const float* A0, const float* A1, const float* A2,
    const float* W0, const float* W1, const float* W2,
    const float* B0, const float* B1, const float* B2,
    const float* ob)
{
    int z = blockIdx.z;
    if (z == 0 && blockIdx.x == 0 && blockIdx.y == 0) {
        float ob0 = ob[0];
        for (int i = threadIdx.x; i < CN; i += 128) {
            g_sl[i] = ob0;
            g_sumb[i] = 0.f;
            g_rowsum[i] = 0.f;
        }
        if (threadIdx.x == 0) { g_cnt1 = 0u; g_cnt2 = 0u; }
    }
    const float* A = z == 0 ? A0 : (z == 1 ? A1 : A2);
    const float* W = z == 0 ? W0 : (z == 1 ? W1 : W2);
    const float* B = z == 0 ? B0 : (z == 1 ? B1 : B2);
    gemm_core<false>(A, nullptr, W, B, nullptr, nullptr,
                     g_tmpb + (size_t)z * CN * HN, nullptr, nullptr, nullptr,
                     HN, HN, 1);
}

// layer 2 (batched). z0: head-fused (no store). z1 -> g_htb. z2 -> g_hp8.
__global__ __launch_bounds__(128) void gemm_l2_k(
    const float* W0, const float* W1, const float* W2,
    const float* B0, const float* B1, const float* B2,
    const float* R0, const float* R1, const float* R2,
    const float* ow)
{
    int z = blockIdx.z;
    const float* W = z == 0 ? W0 : (z == 1 ? W1 : W2);
    const float* B = z == 0 ? B0 : (z == 1 ? B1 : B2);
    const float* R = z == 0 ? R0 : (z == 1 ? R1 : R2);
    __nv_bfloat16* oB = z == 1 ? g_htb : nullptr;
    unsigned char* o8 = z == 2 ? g_hp8 : nullptr;
    const float* hw = z == 0 ? ow : nullptr;
    gemm_core<true>(nullptr, g_tmpb + (size_t)z * CN * HN, W, B, R, nullptr, oB, o8,
                    hw, nullptr, HN, HN, 1);
}

// trans projection: g_trans = g_htb @ proj_w^T, fused row exp-sums.
__global__ __launch_bounds__(128) void gemm_proj_k(const float* W)
{
    gemm_core<true>(nullptr, g_htb, W, nullptr, nullptr, g_trans, nullptr, nullptr,
                    nullptr, g_rowsum, CN, HN, 0);
}

// ---------------------------------------------------------------------------
// term sparse stage v3: ONE WARP PER WORD, weights register-resident.
// Each lane owns elements [lane*16, lane*16+16) of the word's weight vector
// (8 half2 regs). Per state: one uint4 fp8-row load, 8 cvt + 8 h2fma,
// fp32 butterfly reduce. Dedup'd exp-sums into g_sumb. Logits O(1).
// ---------------------------------------------------------------------------
__global__ __launch_bounds__(256) void term_pair_k(
    const float* __restrict__ tow, const float* __restrict__ tob,
    const int* __restrict__ w2s)
{
    int warp = threadIdx.x >> 5, lane = threadIdx.x & 31;
    int v = blockIdx.x * 8 + warp;

    // lane k<8 holds its own state id
    int ck = (lane < 8) ? w2s[v * SPW + lane] : 0;

    // weight slice -> 8 half2 registers
    const float4* wp4 = (const float4*)(tow + (size_t)v * HN);
    unsigned wh[8];
#pragma unroll
    for (int r = 0; r < 4; r++) {
        float4 w4 = wp4[lane * 4 + r];
        __half2 h0 = __floats2half2_rn(w4.x, w4.y);
        __half2 h1 = __floats2half2_rn(w4.z, w4.w);
        wh[2 * r] = *(unsigned*)&h0;
        wh[2 * r + 1] = *(unsigned*)&h1;
    }

    float s[8];
#pragma unroll
    for (int k = 0; k < 8; k++) {
        int c = __shfl_sync(0xffffffffu, ck, k);
        uint4 q = *(const uint4*)(g_hp8 + (size_t)c * HN + lane * 16);
        unsigned acc = 0;
        acc = h2fma(fp8x2_to_h2((unsigned short)(q.x & 0xffffu)), wh[0], acc);
        acc = h2fma(fp8x2_to_h2((unsigned short)(q.x >> 16)),     wh[1], acc);
        acc = h2fma(fp8x2_to_h2((unsigned short)(q.y & 0xffffu)), wh[2], acc);
        acc = h2fma(fp8x2_to_h2((unsigned short)(q.y >> 16)),     wh[3], acc);
        acc = h2fma(fp8x2_to_h2((unsigned short)(q.z & 0xffffu)), wh[4], acc);
        acc = h2fma(fp8x2_to_h2((unsigned short)(q.z >> 16)),     wh[5], acc);
        acc = h2fma(fp8x2_to_h2((unsigned short)(q.w & 0xffffu)), wh[6], acc);
        acc = h2fma(fp8x2_to_h2((unsigned short)(q.w >> 16)),     wh[7], acc);
        float2 f = __half22float2(*(__half2*)&acc);
        float sk = f.x + f.y;
#pragma unroll
        for (int o = 16; o; o >>= 1) sk += __shfl_xor_sync(0xffffffffu, sk, o);
        s[k] = sk;
    }

    // dedup flags computed with full warp active (shfl needs all lanes)
    bool dup = false;
#pragma unroll
    for (int k2 = 0; k2 < 7; k2++) {
        int c2 = __shfl_sync(0xffffffffu, ck, k2);
        if (lane < 8 && k2 < lane && c2 == ck) dup = true;
    }

    if (lane < 8) {
        float mys = s[0];
#pragma unroll
        for (int k = 1; k < 8; k++)
            if (lane == k) mys = s[k];
        float logit = mys + tob[v];
        g_pair[v * SPW + lane] = logit;
        if (!dup) atomicAdd(&g_sumb[ck], __expf(logit));
    }
}

// ---------------------------------------------------------------------------
// fused parallel scan: grid (NCHUNK, BN), 64 threads. Batch-gathers 17
// step matrices into smem (MLP 17), folds with 1 sync/step. Manual grid
// sync; blocks (0,b) finish batch b; block (1,0) start-lse; (0,0) writes out.
// ---------------------------------------------------------------------------
__global__ __launch_bounds__(64) void scan_all_k(
    const int* __restrict__ text, const int* __restrict__ w2s,
    float* __restrict__ out)
{
    __shared__ int sw[CLEN + 1];
    __shared__ int sws[CLEN + 1][8];
    __shared__ float emi[CLEN + 1][8];
    __shared__ float rlz[CLEN + 1][8];
    __shared__ float sMall[CLEN][64];
    __shared__ float bufA[64], bufB[64];
    __shared__ float red2[2];

    int c = blockIdx.x, b = blockIdx.y, tid = threadIdx.x;
    int base = b * TN + c * CLEN;

    if (tid < CLEN + 1) sw[tid] = text[base + tid];
    __syncthreads();
    for (int idx = tid; idx < (CLEN + 1) * 8; idx += 64) {
        int s = idx >> 3, j = idx & 7;
        int st = w2s[sw[s] * 8 + j];
        sws[s][j] = st;
        rlz[s][j] = __logf(g_rowsum[st]);
        if (s >= 1) emi[s][j] = g_pair[sw[s] * 8 + j] - __logf(g_sumb[st]);
    }
    __syncthreads();

    int j = tid >> 3, i = tid & 7;
#pragma unroll
    for (int s = 0; s < CLEN; s++)
        sMall[s][tid] = g_trans[(size_t)sws[s][i] * CN + sws[s + 1][j]]
                        - rlz[s][i] + emi[s + 1][j];
    __syncthreads();

    float* cur = &sMall[0][0];
    float* nxt = bufA;
    float* spare = bufB;
    for (int s = 1; s < CLEN; s++) {
        const float* Mr = &sMall[s][j << 3];
        float v0 = Mr[0] + cur[0 * 8 + i];
        float v1 = Mr[1] + cur[1 * 8 + i];
        float v2 = Mr[2] + cur[2 * 8 + i];
        float v3 = Mr[3] + cur[3 * 8 + i];
        float v4 = Mr[4] + cur[4 * 8 + i];
        float v5 = Mr[5] + cur[5 * 8 + i];
        float v6 = Mr[6] + cur[6 * 8 + i];
        float v7 = Mr[7] + cur[7 * 8 + i];
        float m = fmaxf(fmaxf(fmaxf(v0, v1), fmaxf(v2, v3)),
                        fmaxf(fmaxf(v4, v5), fmaxf(v6, v7)));
        float sum = ((__expf(v0 - m) + __expf(v1 - m)) + (__expf(v2 - m) + __expf(v3 - m))) +
                    ((__expf(v4 - m) + __expf(v5 - m)) + (__expf(v6 - m) + __expf(v7 - m)));
        nxt[tid] = m + __logf(sum);
        __syncthreads();
        float* old = (s == 1) ? spare : cur;
        cur = nxt;
        nxt = old;
    }
    g_chunk[((size_t)b * NCHUNK + c) * 64 + tid] = cur[tid];
    __threadfence();
    __syncthreads();

    if (c == 1 && b == 0) {
        const float4* sl4 = (const float4*)g_sl;
        float es = 0.f;
#pragma unroll
        for (int q = 0; q < 4; q++) {
            float4 v = sl4[tid * 4 + q];
            es += __expf(v.x) + __expf(v.y) + __expf(v.z) + __expf(v.w);
        }
#pragma unroll
        for (int o = 16; o; o >>= 1) es += __shfl_xor_sync(0xffffffffu, es, o);
        if ((tid & 31) == 0) red2[tid >> 5] = es;
        __syncthreads();
        if (tid == 0) {
            g_slse = __logf(red2[0] + red2[1]);
            __threadfence();
        }
        __syncthreads();
    }
    if (tid == 0) atomicAdd(&g_cnt1, 1u);
    if (c != 0) return;

    if (tid == 0) {
        while (atomicAdd(&g_cnt1, 0u) < (unsigned)(NCHUNK * BN)) __nanosleep(64);
    }
    __syncthreads();
    __threadfence();

    if (tid < 8) {
        int c0 = sws[0][tid];
        float an = g_sl[c0] - g_slse + g_pair[sw[0] * 8 + tid] - __logf(g_sumb[c0]);
        float a[8];
#pragma unroll
        for (int q = 0; q < 8; q++) a[q] = __shfl_sync(0xFFu, an, q);
        for (int cc = 0; cc < NCHUNK; cc++) {
            const float4* p4 =
                (const float4*)(g_chunk + ((size_t)b * NCHUNK + cc) * 64 + (tid << 3));
            float4 pA = p4[0], pB = p4[1];
            float v0 = pA.x + a[0], v1 = pA.y + a[1], v2 = pA.z + a[2], v3 = pA.w + a[3];
            float v4 = pB.x + a[4], v5 = pB.y + a[5], v6 = pB.z + a[6], v7 = pB.w + a[7];
            float m = fmaxf(fmaxf(fmaxf(v0, v1), fmaxf(v2, v3)),
                            fmaxf(fmaxf(v4, v5), fmaxf(v6, v7)));
            float s = ((__expf(v0 - m) + __expf(v1 - m)) + (__expf(v2 - m) + __expf(v3 - m))) +
                      ((__expf(v4 - m) + __expf(v5 - m)) + (__expf(v6 - m) + __expf(v7 - m)));
            an = m + __logf(s);
#pragma unroll
            for (int q = 0; q < 8; q++) a[q] = __shfl_sync(0xFFu, an, q);
        }
        if (tid == 0) {
            float m = a[0];
#pragma unroll
            for (int q = 1; q < 8; q++) m = fmaxf(m, a[q]);
            float s = 0.f;
#pragma unroll
            for (int q = 0; q < 8; q++) s += __expf(a[q] - m);
            g_ev[b] = m + __logf(s);
            __threadfence();
            atomicAdd(&g_cnt2, 1u);
        }
    }
    if (b != 0) return;

    if (tid == 0) {
        while (atomicAdd(&g_cnt2, 0u) < (unsigned)BN) __nanosleep(64);
        __threadfence();
        float s = 0.f;
#pragma unroll
        for (int q = 0; q < BN; q++) s += g_ev[q];
        out[0] = s;
    }
}

// ---------------------------------------------------------------------------
extern "C" void kernel_launch(void* const* d_in, const int* in_sizes, int n_in,
                              void* d_out, int out_size)
{
    const float* start_emb = (const float*)d_in[0];
    const float* start_l1w = (const float*)d_in[1];
    const float* start_l1b = (const float*)d_in[2];
    const float* start_l2w = (const float*)d_in[3];
    const float* start_l2b = (const float*)d_in[4];
    const float* start_ow  = (const float*)d_in[5];
    const float* start_ob  = (const float*)d_in[6];
    const float* state_emb = (const float*)d_in[7];
    const float* trans_l1w = (const float*)d_in[8];
    const float* trans_l1b = (const float*)d_in[9];
    const float* trans_l2w = (const float*)d_in[10];
    const float* trans_l2b = (const float*)d_in[11];
    const float* proj_w    = (const float*)d_in[12];
    const float* pret_emb  = (const float*)d_in[13];
    const float* term_l1w  = (const float*)d_in[14];
    const float* term_l1b  = (const float*)d_in[15];
    const float* term_l2w  = (const float*)d_in[16];
    const float* term_l2b  = (const float*)d_in[17];
    const float* term_ow   = (const float*)d_in[18];
    const float* term_ob   = (const float*)d_in[19];
    const int*   text      = (const int*)d_in[20];
    const int*   w2s       = (const int*)d_in[21];
    float* out = (float*)d_out;

    // one-time infra (no device memory): low-priority side stream + events
    static cudaStream_t s1 = nullptr;
    static cudaEvent_t evA = nullptr, evB = nullptr;
    if (s1 == nullptr) {
        int loPri = 0, hiPri = 0;
        cudaDeviceGetStreamPriorityRange(&loPri, &hiPri);
        cudaStreamCreateWithPriority(&s1, cudaStreamNonBlocking, loPri);
        cudaEventCreateWithFlags(&evA, cudaEventDisableTiming);
        cudaEventCreateWithFlags(&evB, cudaEventDisableTiming);
    }
    cudaStream_t s0 = (cudaStream_t)0;  // legacy stream (what the harness captures)

    // 1) layer-1 GEMMs (3 chains, z-batched) + scratch init
    gemm_l1_k<<<dim3(HN / 64, CN / 64, 3), 128, 0, s0>>>(
        start_emb, state_emb, pret_emb,
        start_l1w, trans_l1w, term_l1w,
        start_l1b, trans_l1b, term_l1b,
        start_ob);
    // 2) layer-2 GEMMs (start head fused via atomics; term out in fp8)
    gemm_l2_k<<<dim3(HN / 64, CN / 64, 3), 128, 0, s0>>>(
        start_l2w, trans_l2w, term_l2w,
        start_l2b, trans_l2b, term_l2b,
        start_emb, state_emb, pret_emb,
        start_ow);
    cudaEventRecord(evA, s0);

    // 3) proj (with fused row exp-sums) issued FIRST; the term grid
    //    backfills around it on the low-priority stream.
    gemm_proj_k<<<dim3(CN / 64, CN / 64, 1), 128, 0, s0>>>(proj_w);

    cudaStreamWaitEvent(s1, evA, 0);
    term_pair_k<<<VN / 8, 256, 0, s1>>>(term_ow, term_ob, w2s);
    cudaEventRecord(evB, s1);

    // join, then 4) fused parallel scan + final evidence
    cudaStreamWaitEvent(s0, evB, 0);
    scan_all_k<<<dim3(NCHUNK, BN), 64, 0, s0>>>(text, w2s, out);
}

// round 11
// speedup vs baseline: 3.7227x; 1.0432x over previous
#include <cuda_runtime.h>
#include <cuda_bf16.h>
#include <cuda_fp16.h>
#include <math.h>

#define CN 1024
#define HN 512
#define VN 32000
#define BN 16
#define TN 256
#define SPW 8
#define NCHUNK 15
#define CLEN 17   // 15*17 = 255 step matrices

// ------------------------- scratch (static device memory; no allocs) -------
__device__ __nv_bfloat16 g_tmpb[3 * CN * HN];  // relu(layer1) per chain, bf16
__device__ __nv_bfloat16 g_htb[CN * HN];       // trans residual out (bf16)
__device__ unsigned char g_hp8[CN * HN];       // term residual out (fp8 e4m3)
__device__ __half g_towh[VN * HN];             // term_ow pre-converted to fp16
__device__ float g_sl[CN];                     // start logits (bias + fused head dots)
__device__ float g_slse;                       // lse of start logits
__device__ float g_trans[CN * CN];             // raw trans logits
__device__ float g_rowsum[CN];                 // per-row sum(exp(trans)) (no max; safe)
__device__ float g_pair[VN * SPW];             // term pair logits
__device__ float g_sumb[CN];                   // sum exp(logit) per state
__device__ float g_chunk[BN * NCHUNK * 64];    // chunk products
__device__ float g_ev[BN];
__device__ unsigned g_cnt1;
__device__ unsigned g_cnt2;

// fp8 / half helpers --------------------------------------------------------
__device__ __forceinline__ unsigned fp8x2_to_h2(unsigned short u) {
    unsigned r;
    asm("cvt.rn.f16x2.e4m3x2 %0, %1;" : "=r"(r) : "h"(u));
    return r;
}
__device__ __forceinline__ unsigned h2fma(unsigned a, unsigned b, unsigned c) {
    unsigned d;
    asm("fma.rn.f16x2 %0, %1, %2, %3;" : "=r"(d) : "r"(a), "r"(b), "r"(c));
    return d;
}
__device__ __forceinline__ unsigned short f2_to_fp8x2(float v0, float v1) {
    unsigned short u;  // lo byte = v0, hi byte = v1
    asm("cvt.rn.satfinite.e4m3x2.f32 %0, %1, %2;" : "=h"(u) : "f"(v1), "f"(v0));
    return u;
}

// ---------------------------------------------------------------------------
// bf16 tensor-core GEMM core (R4-proven): CTA 64x64, 128 threads, 2x2 warps,
// warp tile 32x32, K-step 32, register-prefetch, manual LDS fragment loads.
// Fused epilogues: headw (row-dot -> atomicAdd g_sl), rowsum (atomicAdd
// per-row sum of expf(out)), out8 (fp8 store).
// ---------------------------------------------------------------------------
__device__ __forceinline__ void mma16816(float* d, const unsigned* a, const unsigned* b) {
    asm volatile(
        "mma.sync.aligned.m16n8k16.row.col.f32.bf16.bf16.f32 "
        "{%0,%1,%2,%3}, {%4,%5,%6,%7}, {%8,%9}, {%0,%1,%2,%3};\n"
        : "+f"(d[0]), "+f"(d[1]), "+f"(d[2]), "+f"(d[3])
        : "r"(a[0]), "r"(a[1]), "r"(a[2]), "r"(a[3]), "r"(b[0]), "r"(b[1]));
}

#define SSTRIDE 40  // bf16 elems per smem row (80B) -> conflict-free frag loads

template <bool ABF>
__device__ __forceinline__ void gemm_core(
    const float* __restrict__ Af, const __nv_bfloat16* __restrict__ Ab,
    const float* __restrict__ W, const float* __restrict__ bias,
    const float* __restrict__ res, float* __restrict__ outF,
    __nv_bfloat16* __restrict__ outB, unsigned char* __restrict__ out8,
    const float* __restrict__ headw, float* __restrict__ rowsum,
    int N, int K, int relu)
{
    __shared__ __nv_bfloat16 sA[64 * SSTRIDE];
    __shared__ __nv_bfloat16 sB[64 * SSTRIDE];

    const int t = threadIdx.x;
    const int lane = t & 31, warp = t >> 5;
    const int wm = warp >> 1, wn = warp & 1;
    const int row0 = blockIdx.y * 64, col0 = blockIdx.x * 64;
    const int lr = lane >> 2, lc = lane & 3;

    float acc[2][4][4];
#pragma unroll
    for (int mt = 0; mt < 2; mt++)
#pragma unroll
        for (int nt = 0; nt < 4; nt++)
#pragma unroll
            for (int q = 0; q < 4; q++) acc[mt][nt][q] = 0.f;

    float4 pa[4];
    uint2 pab[4];
    float4 pw[4];

#pragma unroll
    for (int i = 0; i < 4; i++) {
        int id = i * 128 + t, r = id >> 3, c4 = id & 7;
        if (ABF)
            pab[i] = *(const uint2*)(Ab + (size_t)(row0 + r) * K + c4 * 4);
        else
            pa[i] = *(const float4*)(Af + (size_t)(row0 + r) * K + c4 * 4);
        pw[i] = *(const float4*)(W + (size_t)(col0 + r) * K + c4 * 4);
    }

    const int NT = K / 32;
    for (int kt = 0; kt < NT; kt++) {
#pragma unroll
        for (int i = 0; i < 4; i++) {
            int id = i * 128 + t, r = id >> 3, c4 = id & 7;
            __nv_bfloat16* da = &sA[r * SSTRIDE + c4 * 4];
            if (ABF) {
                *(unsigned*)da = pab[i].x;
                *(unsigned*)(da + 2) = pab[i].y;
            } else {
                *(__nv_bfloat162*)da = __float22bfloat162_rn(make_float2(pa[i].x, pa[i].y));
                *(__nv_bfloat162*)(da + 2) = __float22bfloat162_rn(make_float2(pa[i].z, pa[i].w));
            }
            __nv_bfloat16* dw = &sB[r * SSTRIDE + c4 * 4];
            *(__nv_bfloat162*)dw = __float22bfloat162_rn(make_float2(pw[i].x, pw[i].y));
            *(__nv_bfloat162*)(dw + 2) = __float22bfloat162_rn(make_float2(pw[i].z, pw[i].w));
        }
        __syncthreads();

        int kn = (kt + 1) * 32;
        if (kn < K) {
#pragma unroll
            for (int i = 0; i < 4; i++) {
                int id = i * 128 + t, r = id >> 3, c4 = id & 7;
                if (ABF)
                    pab[i] = *(const uint2*)(Ab + (size_t)(row0 + r) * K + kn + c4 * 4);
                else
                    pa[i] = *(const float4*)(Af + (size_t)(row0 + r) * K + kn + c4 * 4);
                pw[i] = *(const float4*)(W + (size_t)(col0 + r) * K + kn + c4 * 4);
            }
        }

#pragma unroll
        for (int kk = 0; kk < 2; kk++) {
            unsigned af[2][4], bfr[4][2];
            int kb = kk * 16 + lc * 2;
#pragma unroll
            for (int mt = 0; mt < 2; mt++) {
                const __nv_bfloat16* p = &sA[(wm * 32 + mt * 16 + lr) * SSTRIDE + kb];
                af[mt][0] = *(const unsigned*)p;
                af[mt][1] = *(const unsigned*)(p + 8 * SSTRIDE);
                af[mt][2] = *(const unsigned*)(p + 8);
                af[mt][3] = *(const unsigned*)(p + 8 * SSTRIDE + 8);
            }
#pragma unroll
            for (int nt = 0; nt < 4; nt++) {
                const __nv_bfloat16* p = &sB[(wn * 32 + nt * 8 + lr) * SSTRIDE + kb];
                bfr[nt][0] = *(const unsigned*)p;
                bfr[nt][1] = *(const unsigned*)(p + 8);
            }
#pragma unroll
            for (int mt = 0; mt < 2; mt++)
#pragma unroll
                for (int nt = 0; nt < 4; nt++) mma16816(acc[mt][nt], af[mt], bfr[nt]);
        }
        __syncthreads();
    }

    float part[2][2] = {{0.f, 0.f}, {0.f, 0.f}};
    float rs[2][2] = {{0.f, 0.f}, {0.f, 0.f}};
#pragma unroll
    for (int mt = 0; mt < 2; mt++)
#pragma unroll
        for (int nt = 0; nt < 4; nt++) {
            int gr = row0 + wm * 32 + mt * 16 + lr;
            int gc = col0 + wn * 32 + nt * 8 + lc * 2;
            float2 b2 = make_float2(0.f, 0.f);
            if (bias) b2 = *(const float2*)(bias + gc);
#pragma unroll
            for (int h = 0; h < 2; h++) {
                int r_ = gr + h * 8;
                float v0 = acc[mt][nt][h * 2 + 0] + b2.x;
                float v1 = acc[mt][nt][h * 2 + 1] + b2.y;
                if (relu) { v0 = fmaxf(v0, 0.f); v1 = fmaxf(v1, 0.f); }
                if (res) {
                    float2 r2 = *(const float2*)(res + (size_t)r_ * N + gc);
                    v0 += r2.x; v1 += r2.y;
                }
                if (headw) {
                    float2 wv = *(const float2*)(headw + gc);
                    part[mt][h] = fmaf(v0, wv.x, fmaf(v1, wv.y, part[mt][h]));
                }
                if (rowsum) rs[mt][h] += __expf(v0) + __expf(v1);
                if (outF) *(float2*)(outF + (size_t)r_ * N + gc) = make_float2(v0, v1);
                if (outB)
                    *(__nv_bfloat162*)(outB + (size_t)r_ * N + gc) =
                        __float22bfloat162_rn(make_float2(v0, v1));
                if (out8)
                    *(unsigned short*)(out8 + (size_t)r_ * N + gc) = f2_to_fp8x2(v0, v1);
            }
        }
    if (headw || rowsum) {
#pragma unroll
        for (int mt = 0; mt < 2; mt++)
#pragma unroll
            for (int h = 0; h < 2; h++) {
                float p = headw ? part[mt][h] : rs[mt][h];
                p += __shfl_xor_sync(0xffffffffu, p, 1);
                p += __shfl_xor_sync(0xffffffffu, p, 2);
                if (lc == 0) {
                    int r_ = row0 + wm * 32 + mt * 16 + lr + h * 8;
                    atomicAdd(headw ? &g_sl[r_] : &rowsum[r_], p);
                }
            }
    }
}

// layer 1 (batched over z=3 chains). Block (0,0,0) also initializes scratch.
__global__ __launch_bounds__(128) void gemm_l1_k(
    const float* A0, const float* A1, const float* A2,
    const float* W0, const float* W1, const float* W2,
    const float* B0, const float* B1, const float* B2,
    const float* ob)
{
    int z = blockIdx.z;
    if (z == 0 && blockIdx.x == 0 && blockIdx.y == 0) {
        float ob0 = ob[0];
        for (int i = threadIdx.x; i < CN; i += 128) {
            g_sl[i] = ob0;
            g_sumb[i] = 0.f;
            g_rowsum[i] = 0.f;
        }
        if (threadIdx.x == 0) { g_cnt1 = 0u; g_cnt2 = 0u; }
    }
    const float* A = z == 0 ? A0 : (z == 1 ? A1 : A2);
    const float* W = z == 0 ? W0 : (z == 1 ? W1 : W2);
    const float* B = z == 0 ? B0 : (z == 1 ? B1 : B2);
    gemm_core<false>(A, nullptr, W, B, nullptr, nullptr,
                     g_tmpb + (size_t)z * CN * HN, nullptr, nullptr, nullptr,
                     HN, HN, 1);
}

// layer 2 (batched). z0: head-fused (no store). z1 -> g_htb. z2 -> g_hp8.
__global__ __launch_bounds__(128) void gemm_l2_k(
    const float* W0, const float* W1, const float* W2,
    const float* B0, const float* B1, const float* B2,
    const float* R0, const float* R1, const float* R2,
    const float* ow)
{
    int z = blockIdx.z;
    const float* W = z == 0 ? W0 : (z == 1 ? W1 : W2);
    const float* B = z == 0 ? B0 : (z == 1 ? B1 : B2);
    const float* R = z == 0 ? R0 : (z == 1 ? R1 : R2);
    __nv_bfloat16* oB = z == 1 ? g_htb : nullptr;
    unsigned char* o8 = z == 2 ? g_hp8 : nullptr;
    const float* hw = z == 0 ? ow : nullptr;
    gemm_core<true>(nullptr, g_tmpb + (size_t)z * CN * HN, W, B, R, nullptr, oB, o8,
                    hw, nullptr, HN, HN, 1);
}

// trans projection: g_trans = g_htb @ proj_w^T, fused row exp-sums.
__global__ __launch_bounds__(128) void gemm_proj_k(const float* W)
{
    gemm_core<true>(nullptr, g_htb, W, nullptr, nullptr, g_trans, nullptr, nullptr,
                    nullptr, g_rowsum, CN, HN, 0);
}

// ---------------------------------------------------------------------------
// term weight pre-conversion: fp32 -> fp16 (runs at t=0 on the side stream,
// fully hidden under the l1/l2 GEMMs).
// ---------------------------------------------------------------------------
__global__ __launch_bounds__(256) void convw_k(const float* __restrict__ tow)
{
    size_t i = ((size_t)blockIdx.x * 256 + threadIdx.x) * 8;
    float4 a = *(const float4*)(tow + i);
    float4 b = *(const float4*)(tow + i + 4);
    __half2 h0 = __floats2half2_rn(a.x, a.y);
    __half2 h1 = __floats2half2_rn(a.z, a.w);
    __half2 h2 = __floats2half2_rn(b.x, b.y);
    __half2 h3 = __floats2half2_rn(b.z, b.w);
    uint4 o;
    o.x = *(unsigned*)&h0; o.y = *(unsigned*)&h1;
    o.z = *(unsigned*)&h2; o.w = *(unsigned*)&h3;
    *(uint4*)(g_towh + i) = o;
}

// ---------------------------------------------------------------------------
// term sparse stage v4: ONE WARP PER WORD, fp16 weights register-resident,
// all 8 fp8 rows prefetched (MLP 8). Dedup'd exp-sums into g_sumb.
// ---------------------------------------------------------------------------
__global__ __launch_bounds__(256) void term_pair_k(
    const float* __restrict__ tob, const int* __restrict__ w2s)
{
    int warp = threadIdx.x >> 5, lane = threadIdx.x & 31;
    int v = blockIdx.x * 8 + warp;

    // lane k<8 holds its own state id
    int ck = (lane < 8) ? w2s[v * SPW + lane] : 0;

    // weight slice: 16 fp16 = 32 B per lane -> 8 half2 regs (2 uint4 loads)
    const uint4* wp4 = (const uint4*)(g_towh + (size_t)v * HN);
    uint4 wq0 = wp4[lane * 2], wq1 = wp4[lane * 2 + 1];
    unsigned wh[8] = {wq0.x, wq0.y, wq0.z, wq0.w, wq1.x, wq1.y, wq1.z, wq1.w};

    // broadcast state ids, then prefetch ALL 8 fp8 rows (MLP 8)
    int cs[8];
#pragma unroll
    for (int k = 0; k < 8; k++) cs[k] = __shfl_sync(0xffffffffu, ck, k);
    uint4 q[8];
#pragma unroll
    for (int k = 0; k < 8; k++)
        q[k] = *(const uint4*)(g_hp8 + (size_t)cs[k] * HN + lane * 16);

    float s[8];
#pragma unroll
    for (int k = 0; k < 8; k++) {
        unsigned acc = 0;
        acc = h2fma(fp8x2_to_h2((unsigned short)(q[k].x & 0xffffu)), wh[0], acc);
        acc = h2fma(fp8x2_to_h2((unsigned short)(q[k].x >> 16)),     wh[1], acc);
        acc = h2fma(fp8x2_to_h2((unsigned short)(q[k].y & 0xffffu)), wh[2], acc);
        acc = h2fma(fp8x2_to_h2((unsigned short)(q[k].y >> 16)),     wh[3], acc);
        acc = h2fma(fp8x2_to_h2((unsigned short)(q[k].z & 0xffffu)), wh[4], acc);
        acc = h2fma(fp8x2_to_h2((unsigned short)(q[k].z >> 16)),     wh[5], acc);
        acc = h2fma(fp8x2_to_h2((unsigned short)(q[k].w & 0xffffu)), wh[6], acc);
        acc = h2fma(fp8x2_to_h2((unsigned short)(q[k].w >> 16)),     wh[7], acc);
        float2 f = __half22float2(*(__half2*)&acc);
        float sk = f.x + f.y;
#pragma unroll
        for (int o = 16; o; o >>= 1) sk += __shfl_xor_sync(0xffffffffu, sk, o);
        s[k] = sk;
    }

    // dedup flags (full warp active for shfl)
    bool dup = false;
#pragma unroll
    for (int k2 = 0; k2 < 7; k2++) {
        int c2 = __shfl_sync(0xffffffffu, ck, k2);
        if (lane < 8 && k2 < lane && c2 == ck) dup = true;
    }

    if (lane < 8) {
        float mys = s[0];
#pragma unroll
        for (int k = 1; k < 8; k++)
            if (lane == k) mys = s[k];
        float logit = mys + tob[v];
        g_pair[v * SPW + lane] = logit;
        if (!dup) atomicAdd(&g_sumb[ck], __expf(logit));
    }
}

// ---------------------------------------------------------------------------
// fused parallel scan: grid (NCHUNK, BN), 64 threads. Batch-gathers 17
// step matrices into smem (MLP 17), folds with 1 sync/step. Manual grid
// sync; blocks (0,b) finish batch b; block (1,0) start-lse; (0,0) writes out.
// ---------------------------------------------------------------------------
__global__ __launch_bounds__(64) void scan_all_k(
    const int* __restrict__ text, const int* __restrict__ w2s,
    float* __restrict__ out)
{
    __shared__ int sw[CLEN + 1];
    __shared__ int sws[CLEN + 1][8];
    __shared__ float emi[CLEN + 1][8];
    __shared__ float rlz[CLEN + 1][8];
    __shared__ float sMall[CLEN][64];
    __shared__ float bufA[64], bufB[64];
    __shared__ float red2[2];

    int c = blockIdx.x, b = blockIdx.y, tid = threadIdx.x;
    int base = b * TN + c * CLEN;

    if (tid < CLEN + 1) sw[tid] = text[base + tid];
    __syncthreads();
    for (int idx = tid; idx < (CLEN + 1) * 8; idx += 64) {
        int s = idx >> 3, j = idx & 7;
        int st = w2s[sw[s] * 8 + j];
        sws[s][j] = st;
        rlz[s][j] = __logf(g_rowsum[st]);
        if (s >= 1) emi[s][j] = g_pair[sw[s] * 8 + j] - __logf(g_sumb[st]);
    }
    __syncthreads();

    int j = tid >> 3, i = tid & 7;
#pragma unroll
    for (int s = 0; s < CLEN; s++)
        sMall[s][tid] = g_trans[(size_t)sws[s][i] * CN + sws[s + 1][j]]
                        - rlz[s][i] + emi[s + 1][j];
    __syncthreads();

    float* cur = &sMall[0][0];
    float* nxt = bufA;
    float* spare = bufB;
    for (int s = 1; s < CLEN; s++) {
        const float* Mr = &sMall[s][j << 3];
        float v0 = Mr[0] + cur[0 * 8 + i];
        float v1 = Mr[1] + cur[1 * 8 + i];
        float v2 = Mr[2] + cur[2 * 8 + i];
        float v3 = Mr[3] + cur[3 * 8 + i];
        float v4 = Mr[4] + cur[4 * 8 + i];
        float v5 = Mr[5] + cur[5 * 8 + i];
        float v6 = Mr[6] + cur[6 * 8 + i];
        float v7 = Mr[7] + cur[7 * 8 + i];
        float m = fmaxf(fmaxf(fmaxf(v0, v1), fmaxf(v2, v3)),
                        fmaxf(fmaxf(v4, v5), fmaxf(v6, v7)));
        float sum = ((__expf(v0 - m) + __expf(v1 - m)) + (__expf(v2 - m) + __expf(v3 - m))) +
                    ((__expf(v4 - m) + __expf(v5 - m)) + (__expf(v6 - m) + __expf(v7 - m)));
        nxt[tid] = m + __logf(sum);
        __syncthreads();
        float* old = (s == 1) ? spare : cur;
        cur = nxt;
        nxt = old;
    }
    g_chunk[((size_t)b * NCHUNK + c) * 64 + tid] = cur[tid];
    __threadfence();
    __syncthreads();

    if (c == 1 && b == 0) {
        const float4* sl4 = (const float4*)g_sl;
        float es = 0.f;
#pragma unroll
        for (int q = 0; q < 4; q++) {
            float4 v = sl4[tid * 4 + q];
            es += __expf(v.x) + __expf(v.y) + __expf(v.z) + __expf(v.w);
        }
#pragma unroll
        for (int o = 16; o; o >>= 1) es += __shfl_xor_sync(0xffffffffu, es, o);
        if ((tid & 31) == 0) red2[tid >> 5] = es;
        __syncthreads();
        if (tid == 0) {
            g_slse = __logf(red2[0] + red2[1]);
            __threadfence();
        }
        __syncthreads();
    }
    if (tid == 0) atomicAdd(&g_cnt1, 1u);
    if (c != 0) return;

    if (tid == 0) {
        while (atomicAdd(&g_cnt1, 0u) < (unsigned)(NCHUNK * BN)) __nanosleep(64);
    }
    __syncthreads();
    __threadfence();

    if (tid < 8) {
        int c0 = sws[0][tid];
        float an = g_sl[c0] - g_slse + g_pair[sw[0] * 8 + tid] - __logf(g_sumb[c0]);
        float a[8];
#pragma unroll
        for (int q = 0; q < 8; q++) a[q] = __shfl_sync(0xFFu, an, q);
        for (int cc = 0; cc < NCHUNK; cc++) {
            const float4* p4 =
                (const float4*)(g_chunk + ((size_t)b * NCHUNK + cc) * 64 + (tid << 3));
            float4 pA = p4[0], pB = p4[1];
            float v0 = pA.x + a[0], v1 = pA.y + a[1], v2 = pA.z + a[2], v3 = pA.w + a[3];
            float v4 = pB.x + a[4], v5 = pB.y + a[5], v6 = pB.z + a[6], v7 = pB.w + a[7];
            float m = fmaxf(fmaxf(fmaxf(v0, v1), fmaxf(v2, v3)),
                            fmaxf(fmaxf(v4, v5), fmaxf(v6, v7)));
            float s = ((__expf(v0 - m) + __expf(v1 - m)) + (__expf(v2 - m) + __expf(v3 - m))) +
                      ((__expf(v4 - m) + __expf(v5 - m)) + (__expf(v6 - m) + __expf(v7 - m)));
            an = m + __logf(s);
#pragma unroll
            for (int q = 0; q < 8; q++) a[q] = __shfl_sync(0xFFu, an, q);
        }
        if (tid == 0) {
            float m = a[0];
#pragma unroll
            for (int q = 1; q < 8; q++) m = fmaxf(m, a[q]);
            float s = 0.f;
#pragma unroll
            for (int q = 0; q < 8; q++) s += __expf(a[q] - m);
            g_ev[b] = m + __logf(s);
            __threadfence();
            atomicAdd(&g_cnt2, 1u);
        }
    }
    if (b != 0) return;

    if (tid == 0) {
        while (atomicAdd(&g_cnt2, 0u) < (unsigned)BN) __nanosleep(64);
        __threadfence();
        float s = 0.f;
#pragma unroll
        for (int q = 0; q < BN; q++) s += g_ev[q];
        out[0] = s;
    }
}

// ---------------------------------------------------------------------------
extern "C" void kernel_launch(void* const* d_in, const int* in_sizes, int n_in,
                              void* d_out, int out_size)
{
    const float* start_emb = (const float*)d_in[0];
    const float* start_l1w = (const float*)d_in[1];
    const float* start_l1b = (const float*)d_in[2];
    const float* start_l2w = (const float*)d_in[3];
    const float* start_l2b = (const float*)d_in[4];
    const float* start_ow  = (const float*)d_in[5];
    const float* start_ob  = (const float*)d_in[6];
    const float* state_emb = (const float*)d_in[7];
    const float* trans_l1w = (const float*)d_in[8];
    const float* trans_l1b = (const float*)d_in[9];
    const float* trans_l2w = (const float*)d_in[10];
    const float* trans_l2b = (const float*)d_in[11];
    const float* proj_w    = (const float*)d_in[12];
    const float* pret_emb  = (const float*)d_in[13];
    const float* term_l1w  = (const float*)d_in[14];
    const float* term_l1b  = (const float*)d_in[15];
    const float* term_l2w  = (const float*)d_in[16];
    const float* term_l2b  = (const float*)d_in[17];
    const float* term_ow   = (const float*)d_in[18];
    const float* term_ob   = (const float*)d_in[19];
    const int*   text      = (const int*)d_in[20];
    const int*   w2s       = (const int*)d_in[21];
    float* out = (float*)d_out;

    // one-time infra (no device memory): low-priority side stream + events
    static cudaStream_t s1 = nullptr;
    static cudaEvent_t evA = nullptr, evB = nullptr;
    if (s1 == nullptr) {
        int loPri = 0, hiPri = 0;
        cudaDeviceGetStreamPriorityRange(&loPri, &hiPri);
        cudaStreamCreateWithPriority(&s1, cudaStreamNonBlocking, loPri);
        cudaEventCreateWithFlags(&evA, cudaEventDisableTiming);
        cudaEventCreateWithFlags(&evB, cudaEventDisableTiming);
    }
    cudaStream_t s0 = (cudaStream_t)0;  // legacy stream (what the harness captures)

    // 0) weight pre-conversion on the side stream (no deps; hides under l1/l2)
    convw_k<<<(VN * HN) / (256 * 8), 256, 0, s1>>>(term_ow);

    // 1) layer-1 GEMMs (3 chains, z-batched) + scratch init
    gemm_l1_k<<<dim3(HN / 64, CN / 64, 3), 128, 0, s0>>>(
        start_emb, state_emb, pret_emb,
        start_l1w, trans_l1w, term_l1w,
        start_l1b, trans_l1b, term_l1b,
        start_ob);
    // 2) layer-2 GEMMs (start head fused via atomics; term out in fp8)
    gemm_l2_k<<<dim3(HN / 64, CN / 64, 3), 128, 0, s0>>>(
        start_l2w, trans_l2w, term_l2w,
        start_l2b, trans_l2b, term_l2b,
        start_emb, state_emb, pret_emb,
        start_ow);
    cudaEventRecord(evA, s0);

    // 3) proj (with fused row exp-sums) issued FIRST; the term grid
    //    backfills around it on the low-priority stream.
    gemm_proj_k<<<dim3(CN / 64, CN / 64, 1), 128, 0, s0>>>(proj_w);

    // term stage: after l2 (evA); convw already ordered earlier on s1
    cudaStreamWaitEvent(s1, evA, 0);
    term_pair_k<<<VN / 8, 256, 0, s1>>>(term_ob, w2s);
    cudaEventRecord(evB, s1);

    // join, then 4) fused parallel scan + final evidence
    cudaStreamWaitEvent(s0, evB, 0);
    scan_all_k<<<dim3(NCHUNK, BN), 64, 0, s0>>>(text, w2s, out);
}